// round 2
// baseline (speedup 1.0000x reference)
#include <cuda_runtime.h>
#include <cuda_bf16.h>
#include <cstdint>

// ---------------------------------------------------------------------------
// GPT-2 block, fp32 baseline.
// B=2, S=4096, D=768, H=12, HD=64, INNER=3072. M = B*S = 8192 rows.
// ---------------------------------------------------------------------------

#define Mrows 8192
#define Dm    768
#define D3    2304
#define INNER 3072
#define NHEAD 12
#define HD    64
#define SEQ   4096
#define BATCH 2

// Scratch (static device globals; no runtime allocation allowed)
__device__ float g_xln[Mrows * Dm];
__device__ float g_qkv[Mrows * D3];
__device__ float g_ctx[Mrows * Dm];
__device__ float g_h  [Mrows * Dm];
__device__ float g_yln[Mrows * Dm];
__device__ float g_act[Mrows * INNER];

// ---------------------------------------------------------------------------
// LayerNorm: one block (256 threads) per row of 768
// ---------------------------------------------------------------------------
__global__ void layernorm_kernel(const float* __restrict__ x,
                                 const float* __restrict__ g,
                                 const float* __restrict__ b,
                                 float* __restrict__ y)
{
    __shared__ float red[16];
    const int row = blockIdx.x;
    const float* xr = x + (size_t)row * Dm;
    const int t = threadIdx.x;

    float v0 = xr[t], v1 = xr[t + 256], v2 = xr[t + 512];
    float s  = v0 + v1 + v2;
    float s2 = v0 * v0 + v1 * v1 + v2 * v2;

    #pragma unroll
    for (int o = 16; o >= 1; o >>= 1) {
        s  += __shfl_xor_sync(0xffffffffu, s,  o);
        s2 += __shfl_xor_sync(0xffffffffu, s2, o);
    }
    const int warp = t >> 5, lane = t & 31;
    if (lane == 0) { red[warp] = s; red[8 + warp] = s2; }
    __syncthreads();
    if (warp == 0) {
        float a  = (lane < 8) ? red[lane] : 0.0f;
        float a2 = (lane < 8) ? red[8 + lane] : 0.0f;
        #pragma unroll
        for (int o = 4; o >= 1; o >>= 1) {
            a  += __shfl_xor_sync(0xffffffffu, a,  o);
            a2 += __shfl_xor_sync(0xffffffffu, a2, o);
        }
        if (lane == 0) { red[0] = a; red[1] = a2; }
    }
    __syncthreads();
    const float mean = red[0] * (1.0f / Dm);
    const float var  = red[1] * (1.0f / Dm) - mean * mean;
    const float rstd = rsqrtf(var + 1e-5f);

    float* yr = y + (size_t)row * Dm;
    yr[t]       = (v0 - mean) * rstd * g[t]       + b[t];
    yr[t + 256] = (v1 - mean) * rstd * g[t + 256] + b[t + 256];
    yr[t + 512] = (v2 - mean) * rstd * g[t + 512] + b[t + 512];
}

// ---------------------------------------------------------------------------
// SGEMM: C[M,N] = A[M,K] @ B[K,N] + bias[N] (+ epilogue)
// 128x128 block tile, BK=8, 256 threads, 8x8 microtile per thread.
// EPI: 0 = bias only, 1 = bias + exact GELU, 2 = bias + residual add
// M % 128 == 0, N % 128 == 0, K % 8 == 0 (all true here).
// ---------------------------------------------------------------------------
__device__ __forceinline__ float gelu_exact(float x)
{
    return 0.5f * x * (1.0f + erff(x * 0.70710678118654752f));
}

template <int EPI>
__global__ __launch_bounds__(256, 2)
void sgemm_epi(const float* __restrict__ A, const float* __restrict__ B,
               const float* __restrict__ bias, const float* __restrict__ res,
               float* __restrict__ C, int M, int N, int K)
{
    __shared__ float As[8][128];
    __shared__ float Bs[8][128];

    const int tid  = threadIdx.x;
    const int tx   = tid & 15;
    const int ty   = tid >> 4;
    const int brow = blockIdx.y * 128;
    const int bcol = blockIdx.x * 128;

    const float* Aptr = A + (size_t)(brow + (tid >> 1)) * K + (tid & 1) * 4;
    const float* Bptr = B + (size_t)(tid >> 5) * N + bcol + (tid & 31) * 4;

    float acc[8][8];
    #pragma unroll
    for (int i = 0; i < 8; ++i)
        #pragma unroll
        for (int j = 0; j < 8; ++j) acc[i][j] = 0.0f;

    const int ar = tid >> 1;
    const int ak = (tid & 1) * 4;
    const int bk = tid >> 5;
    const int bc = (tid & 31) * 4;

    for (int k0 = 0; k0 < K; k0 += 8) {
        float4 av = *(const float4*)Aptr;
        float4 bv = *(const float4*)Bptr;
        __syncthreads();
        As[ak + 0][ar] = av.x;
        As[ak + 1][ar] = av.y;
        As[ak + 2][ar] = av.z;
        As[ak + 3][ar] = av.w;
        *(float4*)&Bs[bk][bc] = bv;
        __syncthreads();

        #pragma unroll
        for (int k = 0; k < 8; ++k) {
            float a[8], b[8];
            *(float4*)(a)     = *(const float4*)&As[k][ty * 8];
            *(float4*)(a + 4) = *(const float4*)&As[k][ty * 8 + 4];
            *(float4*)(b)     = *(const float4*)&Bs[k][tx * 8];
            *(float4*)(b + 4) = *(const float4*)&Bs[k][tx * 8 + 4];
            #pragma unroll
            for (int i = 0; i < 8; ++i)
                #pragma unroll
                for (int j = 0; j < 8; ++j)
                    acc[i][j] = fmaf(a[i], b[j], acc[i][j]);
        }
        Aptr += 8;
        Bptr += (size_t)8 * N;
    }

    const float4 bb0 = *(const float4*)(bias + bcol + tx * 8);
    const float4 bb1 = *(const float4*)(bias + bcol + tx * 8 + 4);

    #pragma unroll
    for (int i = 0; i < 8; ++i) {
        const size_t r = (size_t)(brow + ty * 8 + i);
        float o[8];
        o[0] = acc[i][0] + bb0.x; o[1] = acc[i][1] + bb0.y;
        o[2] = acc[i][2] + bb0.z; o[3] = acc[i][3] + bb0.w;
        o[4] = acc[i][4] + bb1.x; o[5] = acc[i][5] + bb1.y;
        o[6] = acc[i][6] + bb1.z; o[7] = acc[i][7] + bb1.w;
        if (EPI == 1) {
            #pragma unroll
            for (int j = 0; j < 8; ++j) o[j] = gelu_exact(o[j]);
        }
        if (EPI == 2) {
            const float4 r0 = *(const float4*)(res + r * N + bcol + tx * 8);
            const float4 r1 = *(const float4*)(res + r * N + bcol + tx * 8 + 4);
            o[0] += r0.x; o[1] += r0.y; o[2] += r0.z; o[3] += r0.w;
            o[4] += r1.x; o[5] += r1.y; o[6] += r1.z; o[7] += r1.w;
        }
        float* cp = C + r * N + bcol + tx * 8;
        *(float4*)(cp)     = make_float4(o[0], o[1], o[2], o[3]);
        *(float4*)(cp + 4) = make_float4(o[4], o[5], o[6], o[7]);
    }
}

// ---------------------------------------------------------------------------
// Causal flash attention, fp32. One block = (64-query tile, one (b,h)).
// 256 threads as 16x16 grid, each thread owns a 4x4 tile of the 64x64
// score block and a 4x4 tile of the 64x64 output accumulator.
// Smem: Qs [d][q] (xor-swizzled), KPs (K as [d][k] swizzled, reused as
// P [q][k] plain), Vs [k][d]. Total exactly 48KB.
// ---------------------------------------------------------------------------
__global__ __launch_bounds__(256, 2)
void flash_attn_kernel(const float* __restrict__ qkv, float* __restrict__ ctx)
{
    __shared__ float Qs [64 * 64];
    __shared__ float KPs[64 * 64];
    __shared__ float Vs [64 * 64];

    const int bh = blockIdx.y;
    const int b  = bh / NHEAD;
    const int h  = bh % NHEAD;
    const int qt = blockIdx.x;
    const int q_base = qt * 64;

    const int tid = threadIdx.x;
    const int tx  = tid & 15;
    const int ty  = tid >> 4;

    const float* base = qkv + (size_t)b * SEQ * D3 + h * HD;

    // Load Q tile (pre-scaled by 1/sqrt(HD)), transposed [d][q], swizzled
    for (int idx = tid; idx < 64 * 64; idx += 256) {
        const int s = idx >> 6, d = idx & 63;
        const int sw = (d & 15) << 2;
        Qs[d * 64 + (s ^ sw)] = base[(size_t)(q_base + s) * D3 + d] * 0.125f;
    }

    float m[4], l[4], acc[4][4];
    #pragma unroll
    for (int i = 0; i < 4; ++i) {
        m[i] = -1e30f; l[i] = 0.0f;
        #pragma unroll
        for (int j = 0; j < 4; ++j) acc[i][j] = 0.0f;
    }

    for (int kt = 0; kt <= qt; ++kt) {
        const int k_base = kt * 64;
        // Load K (transposed+swizzled) and V (natural)
        for (int idx = tid; idx < 64 * 64; idx += 256) {
            const int s = idx >> 6, d = idx & 63;
            const int sw = (d & 15) << 2;
            const float* rowp = base + (size_t)(k_base + s) * D3;
            KPs[d * 64 + (s ^ sw)] = rowp[Dm + d];
            Vs [s * 64 + d]        = rowp[2 * Dm + d];
        }
        __syncthreads();

        // S = Q @ K^T (pre-scaled)
        float sc[4][4];
        #pragma unroll
        for (int i = 0; i < 4; ++i)
            #pragma unroll
            for (int j = 0; j < 4; ++j) sc[i][j] = 0.0f;

        #pragma unroll 4
        for (int d = 0; d < 64; ++d) {
            const int sw = (d & 15) << 2;
            const float4 a4 = *(const float4*)&Qs [d * 64 + ((ty * 4) ^ sw)];
            const float4 b4 = *(const float4*)&KPs[d * 64 + ((tx * 4) ^ sw)];
            const float a[4] = {a4.x, a4.y, a4.z, a4.w};
            const float bb[4] = {b4.x, b4.y, b4.z, b4.w};
            #pragma unroll
            for (int i = 0; i < 4; ++i)
                #pragma unroll
                for (int j = 0; j < 4; ++j)
                    sc[i][j] = fmaf(a[i], bb[j], sc[i][j]);
        }

        // Causal mask on diagonal tile
        if (kt == qt) {
            #pragma unroll
            for (int i = 0; i < 4; ++i)
                #pragma unroll
                for (int j = 0; j < 4; ++j)
                    if (tx * 4 + j > ty * 4 + i) sc[i][j] = -1e30f;
        }

        // Online softmax update
        #pragma unroll
        for (int i = 0; i < 4; ++i) {
            float mc = fmaxf(fmaxf(sc[i][0], sc[i][1]), fmaxf(sc[i][2], sc[i][3]));
            #pragma unroll
            for (int o = 8; o >= 1; o >>= 1)
                mc = fmaxf(mc, __shfl_xor_sync(0xffffffffu, mc, o));
            const float mn = fmaxf(m[i], mc);
            const float alpha = __expf(m[i] - mn);
            float ssum = 0.0f;
            #pragma unroll
            for (int j = 0; j < 4; ++j) {
                const float p = __expf(sc[i][j] - mn);
                sc[i][j] = p;
                ssum += p;
            }
            #pragma unroll
            for (int o = 8; o >= 1; o >>= 1)
                ssum += __shfl_xor_sync(0xffffffffu, ssum, o);
            l[i] = l[i] * alpha + ssum;
            m[i] = mn;
            #pragma unroll
            for (int j = 0; j < 4; ++j) acc[i][j] *= alpha;
        }

        __syncthreads();   // everyone done reading K from KPs
        // Store P into KPs as [q][k]
        #pragma unroll
        for (int i = 0; i < 4; ++i)
            *(float4*)&KPs[(ty * 4 + i) * 64 + tx * 4] =
                make_float4(sc[i][0], sc[i][1], sc[i][2], sc[i][3]);
        __syncthreads();

        // O += P @ V
        #pragma unroll 4
        for (int k = 0; k < 64; ++k) {
            float a[4];
            #pragma unroll
            for (int i = 0; i < 4; ++i) a[i] = KPs[(ty * 4 + i) * 64 + k];
            const float4 b4 = *(const float4*)&Vs[k * 64 + tx * 4];
            const float bb[4] = {b4.x, b4.y, b4.z, b4.w};
            #pragma unroll
            for (int i = 0; i < 4; ++i)
                #pragma unroll
                for (int j = 0; j < 4; ++j)
                    acc[i][j] = fmaf(a[i], bb[j], acc[i][j]);
        }
        __syncthreads();   // done with KPs/Vs before next tile's loads
    }

    // Write ctx: [B,S,D] with head offset
    #pragma unroll
    for (int i = 0; i < 4; ++i) {
        const float inv = 1.0f / l[i];
        const int row = q_base + ty * 4 + i;
        float* cp = ctx + ((size_t)(b * SEQ + row)) * Dm + h * HD + tx * 4;
        *(float4*)cp = make_float4(acc[i][0] * inv, acc[i][1] * inv,
                                   acc[i][2] * inv, acc[i][3] * inv);
    }
}

// ---------------------------------------------------------------------------
// Launch
// ---------------------------------------------------------------------------
extern "C" void kernel_launch(void* const* d_in, const int* in_sizes, int n_in,
                              void* d_out, int out_size)
{
    const float* hidden    = (const float*)d_in[0];
    // d_in[1] = attention_mask (causal, handled analytically)
    const float* ln1_g     = (const float*)d_in[2];
    const float* ln1_b     = (const float*)d_in[3];
    const float* w_attn    = (const float*)d_in[4];
    const float* b_attn    = (const float*)d_in[5];
    const float* w_cproj   = (const float*)d_in[6];
    const float* b_cproj   = (const float*)d_in[7];
    const float* ln2_g     = (const float*)d_in[8];
    const float* ln2_b     = (const float*)d_in[9];
    const float* w_fc      = (const float*)d_in[10];
    const float* b_fc      = (const float*)d_in[11];
    const float* w_fc_proj = (const float*)d_in[12];
    const float* b_fc_proj = (const float*)d_in[13];
    float* out = (float*)d_out;

    float *xln, *qkv, *ctx, *h, *yln, *act;
    cudaGetSymbolAddress((void**)&xln, g_xln);
    cudaGetSymbolAddress((void**)&qkv, g_qkv);
    cudaGetSymbolAddress((void**)&ctx, g_ctx);
    cudaGetSymbolAddress((void**)&h,   g_h);
    cudaGetSymbolAddress((void**)&yln, g_yln);
    cudaGetSymbolAddress((void**)&act, g_act);

    // 1. LN1
    layernorm_kernel<<<Mrows, 256>>>(hidden, ln1_g, ln1_b, xln);
    // 2. QKV projection
    sgemm_epi<0><<<dim3(D3 / 128, Mrows / 128), 256>>>(
        xln, w_attn, b_attn, nullptr, qkv, Mrows, D3, Dm);
    // 3. Causal flash attention
    flash_attn_kernel<<<dim3(SEQ / 64, BATCH * NHEAD), 256>>>(qkv, ctx);
    // 4. Output projection + residual
    sgemm_epi<2><<<dim3(Dm / 128, Mrows / 128), 256>>>(
        ctx, w_cproj, b_cproj, hidden, h, Mrows, Dm, Dm);
    // 5. LN2
    layernorm_kernel<<<Mrows, 256>>>(h, ln2_g, ln2_b, yln);
    // 6. FC + GELU
    sgemm_epi<1><<<dim3(INNER / 128, Mrows / 128), 256>>>(
        yln, w_fc, b_fc, nullptr, act, Mrows, INNER, Dm);
    // 7. FC projection + residual -> output
    sgemm_epi<2><<<dim3(Dm / 128, Mrows / 128), 256>>>(
        act, w_fc_proj, b_fc_proj, h, out, Mrows, Dm, INNER);
}

// round 7
// speedup vs baseline: 1.6846x; 1.6846x over previous
#include <cuda_runtime.h>
#include <cuda_bf16.h>
#include <cstdint>

// ---------------------------------------------------------------------------
// GPT-2 block. B=2, S=4096, D=768, H=12, HD=64, INNER=3072. M = B*S = 8192.
// GEMMs via mma.sync bf16 (3-split hi/lo for ~fp32 accuracy), flash fp32.
// ---------------------------------------------------------------------------

#define Mrows  8192
#define Dm     768
#define D3     2304
#define INNERD 3072
#define NHEAD  12
#define HD     64
#define SEQ    4096
#define BATCH  2

// ------------------------------- scratch -----------------------------------
__device__ float g_qkv[Mrows * D3];
__device__ float g_h  [Mrows * Dm];

__device__ __nv_bfloat16 g_xln_hi[Mrows * Dm];
__device__ __nv_bfloat16 g_xln_lo[Mrows * Dm];
__device__ __nv_bfloat16 g_ctx_hi[Mrows * Dm];
__device__ __nv_bfloat16 g_ctx_lo[Mrows * Dm];
__device__ __nv_bfloat16 g_yln_hi[Mrows * Dm];
__device__ __nv_bfloat16 g_yln_lo[Mrows * Dm];
__device__ __nv_bfloat16 g_act_hi[Mrows * INNERD];
__device__ __nv_bfloat16 g_act_lo[Mrows * INNERD];

__device__ __nv_bfloat16 g_wT_attn_hi[D3 * Dm];
__device__ __nv_bfloat16 g_wT_attn_lo[D3 * Dm];
__device__ __nv_bfloat16 g_wT_cprj_hi[Dm * Dm];
__device__ __nv_bfloat16 g_wT_cprj_lo[Dm * Dm];
__device__ __nv_bfloat16 g_wT_fc_hi  [INNERD * Dm];
__device__ __nv_bfloat16 g_wT_fc_lo  [INNERD * Dm];
__device__ __nv_bfloat16 g_wT_fcp_hi [Dm * INNERD];
__device__ __nv_bfloat16 g_wT_fcp_lo [Dm * INNERD];

// --------------------------- PTX helpers -----------------------------------
__device__ __forceinline__ uint32_t smem_u32(const void* p) {
    uint32_t a;
    asm("{ .reg .u64 t; cvta.to.shared.u64 t, %1; cvt.u32.u64 %0, t; }"
        : "=r"(a) : "l"(p));
    return a;
}

__device__ __forceinline__ void cpasync16(uint32_t dst, const void* src) {
    asm volatile("cp.async.cg.shared.global [%0], [%1], 16;"
                 :: "r"(dst), "l"(src));
}
__device__ __forceinline__ void cp_commit() {
    asm volatile("cp.async.commit_group;" ::: "memory");
}
__device__ __forceinline__ void cp_wait1() {
    asm volatile("cp.async.wait_group 1;" ::: "memory");
}

#define LDSM4(r0, r1, r2, r3, addr) \
    asm volatile("ldmatrix.sync.aligned.m8n8.x4.shared.b16 {%0,%1,%2,%3}, [%4];" \
                 : "=r"(r0), "=r"(r1), "=r"(r2), "=r"(r3) : "r"(addr))

__device__ __forceinline__ void mma16816(float* d, const uint32_t* a,
                                         const uint32_t* b) {
    asm volatile(
        "mma.sync.aligned.m16n8k16.row.col.f32.bf16.bf16.f32 "
        "{%0,%1,%2,%3}, {%4,%5,%6,%7}, {%8,%9}, {%0,%1,%2,%3};"
        : "+f"(d[0]), "+f"(d[1]), "+f"(d[2]), "+f"(d[3])
        : "r"(a[0]), "r"(a[1]), "r"(a[2]), "r"(a[3]), "r"(b[0]), "r"(b[1]));
}

// ---------------------------------------------------------------------------
// Weight prep: W[K,N] fp32 -> T[N,K] bf16 hi + lo (transpose + split)
// ---------------------------------------------------------------------------
__global__ void wprep(const float* __restrict__ W,
                      __nv_bfloat16* __restrict__ Thi,
                      __nv_bfloat16* __restrict__ Tlo, int K, int N)
{
    __shared__ float t[32][33];
    const int n0 = blockIdx.x * 32, k0 = blockIdx.y * 32;
    const int tx = threadIdx.x, ty = threadIdx.y;
    #pragma unroll
    for (int i = 0; i < 4; ++i)
        t[ty + i * 8][tx] = W[(size_t)(k0 + ty + i * 8) * N + n0 + tx];
    __syncthreads();
    #pragma unroll
    for (int i = 0; i < 4; ++i) {
        const float f = t[tx][ty + i * 8];
        const __nv_bfloat16 hi = __float2bfloat16(f);
        const float lo = f - __bfloat162float(hi);
        const size_t o = (size_t)(n0 + ty + i * 8) * K + k0 + tx;
        Thi[o] = hi;
        Tlo[o] = __float2bfloat16(lo);
    }
}

// ---------------------------------------------------------------------------
// LayerNorm producing bf16 hi/lo split
// ---------------------------------------------------------------------------
__global__ void layernorm_hilo(const float* __restrict__ x,
                               const float* __restrict__ g,
                               const float* __restrict__ b,
                               __nv_bfloat16* __restrict__ yhi,
                               __nv_bfloat16* __restrict__ ylo)
{
    __shared__ float red[16];
    const int row = blockIdx.x;
    const float* xr = x + (size_t)row * Dm;
    const int t = threadIdx.x;

    float v0 = xr[t], v1 = xr[t + 256], v2 = xr[t + 512];
    float s  = v0 + v1 + v2;
    float s2 = v0 * v0 + v1 * v1 + v2 * v2;

    #pragma unroll
    for (int o = 16; o >= 1; o >>= 1) {
        s  += __shfl_xor_sync(0xffffffffu, s,  o);
        s2 += __shfl_xor_sync(0xffffffffu, s2, o);
    }
    const int warp = t >> 5, lane = t & 31;
    if (lane == 0) { red[warp] = s; red[8 + warp] = s2; }
    __syncthreads();
    if (warp == 0) {
        float a  = (lane < 8) ? red[lane] : 0.0f;
        float a2 = (lane < 8) ? red[8 + lane] : 0.0f;
        #pragma unroll
        for (int o = 4; o >= 1; o >>= 1) {
            a  += __shfl_xor_sync(0xffffffffu, a,  o);
            a2 += __shfl_xor_sync(0xffffffffu, a2, o);
        }
        if (lane == 0) { red[0] = a; red[1] = a2; }
    }
    __syncthreads();
    const float mean = red[0] * (1.0f / Dm);
    const float var  = red[1] * (1.0f / Dm) - mean * mean;
    const float rstd = rsqrtf(var + 1e-5f);

    const size_t rb = (size_t)row * Dm;
    #pragma unroll
    for (int i = 0; i < 3; ++i) {
        const int c = t + i * 256;
        const float v = (i == 0) ? v0 : (i == 1) ? v1 : v2;
        const float f = (v - mean) * rstd * g[c] + b[c];
        const __nv_bfloat16 hi = __float2bfloat16(f);
        yhi[rb + c] = hi;
        ylo[rb + c] = __float2bfloat16(f - __bfloat162float(hi));
    }
}

// ---------------------------------------------------------------------------
// mma.sync GEMM: C[M,N] = A[M,K] @ T[N,K]^T + bias (3-split bf16, fp32 acc)
// 128x128 CTA tile, 8 warps (2x4), 64x32 warp tile, BK=32, 3-stage cp.async.
// Smem rows padded to 80B => conflict-free ldmatrix.
// EPI 0: fp32 + bias; EPI 2: fp32 + bias + residual;
// EPI 3: bias + exact GELU -> bf16 hi/lo.
// ---------------------------------------------------------------------------
__device__ __forceinline__ float gelu_exact(float x) {
    return 0.5f * x * (1.0f + erff(x * 0.70710678118654752f));
}

#define ROWB      80            // bytes per smem row (64B data + 16B pad)
#define ARRB      (128 * ROWB)  // 10240 bytes per operand tile
#define BUFB      (4 * ARRB)    // 40960 bytes per stage
#define NSTAGE    3
#define GSMEM_SIZE (NSTAGE * BUFB)

template <int EPI>
__global__ __launch_bounds__(256)
void gemm_mma(const __nv_bfloat16* __restrict__ Ahi, const __nv_bfloat16* __restrict__ Alo,
              const __nv_bfloat16* __restrict__ Bhi, const __nv_bfloat16* __restrict__ Blo,
              const float* __restrict__ bias, const float* __restrict__ res,
              float* __restrict__ C,
              __nv_bfloat16* __restrict__ Chi, __nv_bfloat16* __restrict__ Clo,
              int M, int N, int K)
{
    extern __shared__ char smem[];
    const uint32_t sbase = smem_u32(smem);
    const int tid  = threadIdx.x;
    const int wid  = tid >> 5;
    const int lane = tid & 31;
    const int brow = blockIdx.y * 128;
    const int bcol = blockIdx.x * 128;

    // ---- staging assignment: 4 operand arrays x 64 threads each ----
    const int arr  = tid >> 6;       // 0:Ahi 1:Alo 2:Bhi 3:Blo
    const int u    = tid & 63;
    const int rowb = u >> 2;         // 0..15
    const int chk  = u & 3;          // 16B chunk within 64B row
    const __nv_bfloat16* gsel =
        (arr == 0) ? Ahi : (arr == 1) ? Alo : (arr == 2) ? Bhi : Blo;
    const int gbase_row = (arr < 2) ? brow : bcol;
    const char* gsrc = (const char*)(gsel + (size_t)(gbase_row + rowb) * K) + chk * 16;
    const uint32_t sdst0 = sbase + arr * ARRB + rowb * ROWB + chk * 16;
    const size_t grow16 = (size_t)16 * K * 2;   // 16 rows in bytes

    const int NC = K >> 5;           // K / 32

    // ---- mma fragment addressing ----
    const int m0 = (wid >> 2) * 64;  // warp m-origin within tile
    const int n0 = (wid & 3) * 32;   // warp n-origin
    const int a_r = (lane & 7) + ((lane >> 3) & 1) * 8;
    const int a_k = ((lane >> 4) & 1) * 16;
    const int b_r = (lane & 7) + ((lane >> 4) & 1) * 8;
    const int b_k = ((lane >> 3) & 1) * 16;
    const uint32_t aoff = (uint32_t)((m0 + a_r) * ROWB + a_k);
    const uint32_t boff = (uint32_t)((n0 + b_r) * ROWB + b_k);

    float d[4][4][4];
    #pragma unroll
    for (int mi = 0; mi < 4; ++mi)
        #pragma unroll
        for (int ni = 0; ni < 4; ++ni)
            #pragma unroll
            for (int q = 0; q < 4; ++q) d[mi][ni][q] = 0.0f;

    // ---- prologue: stage chunks 0 and 1 ----
    #pragma unroll
    for (int c = 0; c < 2; ++c) {
        const uint32_t sd = sdst0 + (uint32_t)c * BUFB;
        const char* gs = gsrc + (size_t)c * 64;
        #pragma unroll
        for (int j = 0; j < 8; ++j)
            cpasync16(sd + j * (16 * ROWB), gs + j * grow16);
        cp_commit();
    }

    for (int c = 0; c < NC; ++c) {
        cp_wait1();
        __syncthreads();

        // stage chunk c+2 into buffer (c+2)%3 (buffer last used by compute c-1)
        if (c + 2 < NC) {
            const uint32_t sd = sdst0 + (uint32_t)((c + 2) % NSTAGE) * BUFB;
            const char* gs = gsrc + (size_t)(c + 2) * 64;
            #pragma unroll
            for (int j = 0; j < 8; ++j)
                cpasync16(sd + j * (16 * ROWB), gs + j * grow16);
        }
        cp_commit();   // always commit (possibly empty) to keep group count fixed

        // ---- compute on buffer c%3 ----
        const uint32_t bufb = sbase + (uint32_t)(c % NSTAGE) * BUFB;
        #pragma unroll
        for (int ks = 0; ks < 2; ++ks) {
            const uint32_t kb = ks * 32;
            uint32_t ah[4][4], al[4][4], bh[4][2], bl[4][2];
            #pragma unroll
            for (int mi = 0; mi < 4; ++mi) {
                LDSM4(ah[mi][0], ah[mi][1], ah[mi][2], ah[mi][3],
                      bufb + aoff + mi * (16 * ROWB) + kb);
                LDSM4(al[mi][0], al[mi][1], al[mi][2], al[mi][3],
                      bufb + ARRB + aoff + mi * (16 * ROWB) + kb);
            }
            #pragma unroll
            for (int nj = 0; nj < 2; ++nj) {
                LDSM4(bh[nj * 2][0], bh[nj * 2][1], bh[nj * 2 + 1][0], bh[nj * 2 + 1][1],
                      bufb + 2 * ARRB + boff + nj * (16 * ROWB) + kb);
                LDSM4(bl[nj * 2][0], bl[nj * 2][1], bl[nj * 2 + 1][0], bl[nj * 2 + 1][1],
                      bufb + 3 * ARRB + boff + nj * (16 * ROWB) + kb);
            }
            #pragma unroll
            for (int mi = 0; mi < 4; ++mi)
                #pragma unroll
                for (int ni = 0; ni < 4; ++ni) {
                    mma16816(d[mi][ni], ah[mi], bh[ni]);
                    mma16816(d[mi][ni], ah[mi], bl[ni]);
                    mma16816(d[mi][ni], al[mi], bh[ni]);
                }
        }
    }

    // ---- epilogue ----
    const int tr = lane >> 2;
    const int tc = (lane & 3) * 2;
    #pragma unroll
    for (int mi = 0; mi < 4; ++mi) {
        #pragma unroll
        for (int half = 0; half < 2; ++half) {
            const int row = brow + m0 + mi * 16 + tr + half * 8;
            #pragma unroll
            for (int ni = 0; ni < 4; ++ni) {
                const int col = bcol + n0 + ni * 8 + tc;
                const float2 bv = *(const float2*)(bias + col);
                float v0 = d[mi][ni][half * 2 + 0] + bv.x;
                float v1 = d[mi][ni][half * 2 + 1] + bv.y;
                if (EPI == 2) {
                    const float2 rv = *(const float2*)(res + (size_t)row * N + col);
                    v0 += rv.x; v1 += rv.y;
                }
                if (EPI == 3) {
                    const float gq0 = gelu_exact(v0);
                    const float gq1 = gelu_exact(v1);
                    const __nv_bfloat162 h2 = __floats2bfloat162_rn(gq0, gq1);
                    const __nv_bfloat162 l2 = __floats2bfloat162_rn(
                        gq0 - __low2float(h2), gq1 - __high2float(h2));
                    *(__nv_bfloat162*)(Chi + (size_t)row * N + col) = h2;
                    *(__nv_bfloat162*)(Clo + (size_t)row * N + col) = l2;
                } else {
                    *(float2*)(C + (size_t)row * N + col) = make_float2(v0, v1);
                }
            }
        }
    }
}

// ---------------------------------------------------------------------------
// Causal flash attention, fp32; epilogue emits ctx bf16 hi/lo
// ---------------------------------------------------------------------------
__global__ __launch_bounds__(256, 2)
void flash_attn_kernel(const float* __restrict__ qkv,
                       __nv_bfloat16* __restrict__ chi,
                       __nv_bfloat16* __restrict__ clo)
{
    __shared__ float Qs [64 * 64];
    __shared__ float KPs[64 * 64];
    __shared__ float Vs [64 * 64];

    const int bh = blockIdx.y;
    const int b  = bh / NHEAD;
    const int h  = bh % NHEAD;
    const int qt = blockIdx.x;
    const int q_base = qt * 64;

    const int tid = threadIdx.x;
    const int tx  = tid & 15;
    const int ty  = tid >> 4;

    const float* base = qkv + (size_t)b * SEQ * D3 + h * HD;

    for (int idx = tid; idx < 64 * 64; idx += 256) {
        const int s = idx >> 6, d = idx & 63;
        const int sw = (d & 15) << 2;
        Qs[d * 64 + (s ^ sw)] = base[(size_t)(q_base + s) * D3 + d] * 0.125f;
    }

    float m[4], l[4], acc[4][4];
    #pragma unroll
    for (int i = 0; i < 4; ++i) {
        m[i] = -1e30f; l[i] = 0.0f;
        #pragma unroll
        for (int j = 0; j < 4; ++j) acc[i][j] = 0.0f;
    }

    for (int kt = 0; kt <= qt; ++kt) {
        const int k_base = kt * 64;
        for (int idx = tid; idx < 64 * 64; idx += 256) {
            const int s = idx >> 6, d = idx & 63;
            const int sw = (d & 15) << 2;
            const float* rowp = base + (size_t)(k_base + s) * D3;
            KPs[d * 64 + (s ^ sw)] = rowp[Dm + d];
            Vs [s * 64 + d]        = rowp[2 * Dm + d];
        }
        __syncthreads();

        float sc[4][4];
        #pragma unroll
        for (int i = 0; i < 4; ++i)
            #pragma unroll
            for (int j = 0; j < 4; ++j) sc[i][j] = 0.0f;

        #pragma unroll 4
        for (int d = 0; d < 64; ++d) {
            const int sw = (d & 15) << 2;
            const float4 a4 = *(const float4*)&Qs [d * 64 + ((ty * 4) ^ sw)];
            const float4 b4 = *(const float4*)&KPs[d * 64 + ((tx * 4) ^ sw)];
            const float a[4]  = {a4.x, a4.y, a4.z, a4.w};
            const float bb[4] = {b4.x, b4.y, b4.z, b4.w};
            #pragma unroll
            for (int i = 0; i < 4; ++i)
                #pragma unroll
                for (int j = 0; j < 4; ++j)
                    sc[i][j] = fmaf(a[i], bb[j], sc[i][j]);
        }

        if (kt == qt) {
            #pragma unroll
            for (int i = 0; i < 4; ++i)
                #pragma unroll
                for (int j = 0; j < 4; ++j)
                    if (tx * 4 + j > ty * 4 + i) sc[i][j] = -1e30f;
        }

        #pragma unroll
        for (int i = 0; i < 4; ++i) {
            float mc = fmaxf(fmaxf(sc[i][0], sc[i][1]), fmaxf(sc[i][2], sc[i][3]));
            #pragma unroll
            for (int o = 8; o >= 1; o >>= 1)
                mc = fmaxf(mc, __shfl_xor_sync(0xffffffffu, mc, o));
            const float mn = fmaxf(m[i], mc);
            const float alpha = __expf(m[i] - mn);
            float ssum = 0.0f;
            #pragma unroll
            for (int j = 0; j < 4; ++j) {
                const float p = __expf(sc[i][j] - mn);
                sc[i][j] = p;
                ssum += p;
            }
            #pragma unroll
            for (int o = 8; o >= 1; o >>= 1)
                ssum += __shfl_xor_sync(0xffffffffu, ssum, o);
            l[i] = l[i] * alpha + ssum;
            m[i] = mn;
            #pragma unroll
            for (int j = 0; j < 4; ++j) acc[i][j] *= alpha;
        }

        __syncthreads();
        #pragma unroll
        for (int i = 0; i < 4; ++i)
            *(float4*)&KPs[(ty * 4 + i) * 64 + tx * 4] =
                make_float4(sc[i][0], sc[i][1], sc[i][2], sc[i][3]);
        __syncthreads();

        #pragma unroll 4
        for (int k = 0; k < 64; ++k) {
            float a[4];
            #pragma unroll
            for (int i = 0; i < 4; ++i) a[i] = KPs[(ty * 4 + i) * 64 + k];
            const float4 b4 = *(const float4*)&Vs[k * 64 + tx * 4];
            const float bb[4] = {b4.x, b4.y, b4.z, b4.w};
            #pragma unroll
            for (int i = 0; i < 4; ++i)
                #pragma unroll
                for (int j = 0; j < 4; ++j)
                    acc[i][j] = fmaf(a[i], bb[j], acc[i][j]);
        }
        __syncthreads();
    }

    #pragma unroll
    for (int i = 0; i < 4; ++i) {
        const float inv = 1.0f / l[i];
        const int row = q_base + ty * 4 + i;
        const size_t o = ((size_t)(b * SEQ + row)) * Dm + h * HD + tx * 4;
        const float o0 = acc[i][0] * inv, o1 = acc[i][1] * inv;
        const float o2 = acc[i][2] * inv, o3 = acc[i][3] * inv;
        const __nv_bfloat162 h01 = __floats2bfloat162_rn(o0, o1);
        const __nv_bfloat162 h23 = __floats2bfloat162_rn(o2, o3);
        const __nv_bfloat162 l01 =
            __floats2bfloat162_rn(o0 - __low2float(h01), o1 - __high2float(h01));
        const __nv_bfloat162 l23 =
            __floats2bfloat162_rn(o2 - __low2float(h23), o3 - __high2float(h23));
        *(__nv_bfloat162*)(chi + o)     = h01;
        *(__nv_bfloat162*)(chi + o + 2) = h23;
        *(__nv_bfloat162*)(clo + o)     = l01;
        *(__nv_bfloat162*)(clo + o + 2) = l23;
    }
}

// ---------------------------------------------------------------------------
// Launch
// ---------------------------------------------------------------------------
extern "C" void kernel_launch(void* const* d_in, const int* in_sizes, int n_in,
                              void* d_out, int out_size)
{
    const float* hidden    = (const float*)d_in[0];
    const float* ln1_g     = (const float*)d_in[2];
    const float* ln1_b     = (const float*)d_in[3];
    const float* w_attn    = (const float*)d_in[4];
    const float* b_attn    = (const float*)d_in[5];
    const float* w_cproj   = (const float*)d_in[6];
    const float* b_cproj   = (const float*)d_in[7];
    const float* ln2_g     = (const float*)d_in[8];
    const float* ln2_b     = (const float*)d_in[9];
    const float* w_fc      = (const float*)d_in[10];
    const float* b_fc      = (const float*)d_in[11];
    const float* w_fc_proj = (const float*)d_in[12];
    const float* b_fc_proj = (const float*)d_in[13];
    float* out = (float*)d_out;

    float *qkv, *h;
    __nv_bfloat16 *xh, *xl, *ch, *cl, *yh, *yl, *ah, *al;
    __nv_bfloat16 *wah, *wal, *wch, *wcl, *wfh, *wfl, *wph, *wpl;
    cudaGetSymbolAddress((void**)&qkv, g_qkv);
    cudaGetSymbolAddress((void**)&h,   g_h);
    cudaGetSymbolAddress((void**)&xh, g_xln_hi);  cudaGetSymbolAddress((void**)&xl, g_xln_lo);
    cudaGetSymbolAddress((void**)&ch, g_ctx_hi);  cudaGetSymbolAddress((void**)&cl, g_ctx_lo);
    cudaGetSymbolAddress((void**)&yh, g_yln_hi);  cudaGetSymbolAddress((void**)&yl, g_yln_lo);
    cudaGetSymbolAddress((void**)&ah, g_act_hi);  cudaGetSymbolAddress((void**)&al, g_act_lo);
    cudaGetSymbolAddress((void**)&wah, g_wT_attn_hi); cudaGetSymbolAddress((void**)&wal, g_wT_attn_lo);
    cudaGetSymbolAddress((void**)&wch, g_wT_cprj_hi); cudaGetSymbolAddress((void**)&wcl, g_wT_cprj_lo);
    cudaGetSymbolAddress((void**)&wfh, g_wT_fc_hi);   cudaGetSymbolAddress((void**)&wfl, g_wT_fc_lo);
    cudaGetSymbolAddress((void**)&wph, g_wT_fcp_hi);  cudaGetSymbolAddress((void**)&wpl, g_wT_fcp_lo);

    cudaFuncSetAttribute(gemm_mma<0>, cudaFuncAttributeMaxDynamicSharedMemorySize, GSMEM_SIZE);
    cudaFuncSetAttribute(gemm_mma<2>, cudaFuncAttributeMaxDynamicSharedMemorySize, GSMEM_SIZE);
    cudaFuncSetAttribute(gemm_mma<3>, cudaFuncAttributeMaxDynamicSharedMemorySize, GSMEM_SIZE);

    const dim3 tb(32, 8);
    wprep<<<dim3(D3 / 32,     Dm / 32),     tb>>>(w_attn,    wah, wal, Dm,     D3);
    wprep<<<dim3(Dm / 32,     Dm / 32),     tb>>>(w_cproj,   wch, wcl, Dm,     Dm);
    wprep<<<dim3(INNERD / 32, Dm / 32),     tb>>>(w_fc,      wfh, wfl, Dm,     INNERD);
    wprep<<<dim3(Dm / 32,     INNERD / 32), tb>>>(w_fc_proj, wph, wpl, INNERD, Dm);

    // 1. LN1 -> bf16 hi/lo
    layernorm_hilo<<<Mrows, 256>>>(hidden, ln1_g, ln1_b, xh, xl);
    // 2. QKV projection (fp32 out)
    gemm_mma<0><<<dim3(D3 / 128, Mrows / 128), 256, GSMEM_SIZE>>>(
        xh, xl, wah, wal, b_attn, nullptr, qkv, nullptr, nullptr, Mrows, D3, Dm);
    // 3. Flash attention -> ctx hi/lo
    flash_attn_kernel<<<dim3(SEQ / 64, BATCH * NHEAD), 256>>>(qkv, ch, cl);
    // 4. cproj + residual -> h (fp32)
    gemm_mma<2><<<dim3(Dm / 128, Mrows / 128), 256, GSMEM_SIZE>>>(
        ch, cl, wch, wcl, b_cproj, hidden, h, nullptr, nullptr, Mrows, Dm, Dm);
    // 5. LN2 -> yln hi/lo
    layernorm_hilo<<<Mrows, 256>>>(h, ln2_g, ln2_b, yh, yl);
    // 6. fc + GELU -> act hi/lo (bf16)
    gemm_mma<3><<<dim3(INNERD / 128, Mrows / 128), 256, GSMEM_SIZE>>>(
        yh, yl, wfh, wfl, b_fc, nullptr, nullptr, ah, al, Mrows, INNERD, Dm);
    // 7. fc_proj + residual -> out (fp32)
    gemm_mma<2><<<dim3(Dm / 128, Mrows / 128), 256, GSMEM_SIZE>>>(
        ah, al, wph, wpl, b_fc_proj, h, out, nullptr, nullptr, Mrows, Dm, INNERD);
}

// round 10
// speedup vs baseline: 1.9305x; 1.1460x over previous
#include <cuda_runtime.h>
#include <cuda_bf16.h>
#include <cstdint>

// ---------------------------------------------------------------------------
// GPT-2 block. B=2, S=4096, D=768, H=12, HD=64, INNER=3072. M = B*S = 8192.
// GEMMs + flash attention all via mma.sync bf16 (3-split hi/lo, fp32 accum).
// ---------------------------------------------------------------------------

#define Mrows  8192
#define Dm     768
#define D3     2304
#define INNERD 3072
#define NHEAD  12
#define HD     64
#define SEQ    4096
#define BATCH  2

// ------------------------------- scratch -----------------------------------
__device__ float g_h[Mrows * Dm];

__device__ __nv_bfloat16 g_qkv_hi[Mrows * D3];
__device__ __nv_bfloat16 g_qkv_lo[Mrows * D3];
__device__ __nv_bfloat16 g_xln_hi[Mrows * Dm];
__device__ __nv_bfloat16 g_xln_lo[Mrows * Dm];
__device__ __nv_bfloat16 g_ctx_hi[Mrows * Dm];
__device__ __nv_bfloat16 g_ctx_lo[Mrows * Dm];
__device__ __nv_bfloat16 g_yln_hi[Mrows * Dm];
__device__ __nv_bfloat16 g_yln_lo[Mrows * Dm];
__device__ __nv_bfloat16 g_act_hi[Mrows * INNERD];
__device__ __nv_bfloat16 g_act_lo[Mrows * INNERD];

__device__ __nv_bfloat16 g_wT_attn_hi[D3 * Dm];
__device__ __nv_bfloat16 g_wT_attn_lo[D3 * Dm];
__device__ __nv_bfloat16 g_wT_cprj_hi[Dm * Dm];
__device__ __nv_bfloat16 g_wT_cprj_lo[Dm * Dm];
__device__ __nv_bfloat16 g_wT_fc_hi  [INNERD * Dm];
__device__ __nv_bfloat16 g_wT_fc_lo  [INNERD * Dm];
__device__ __nv_bfloat16 g_wT_fcp_hi [Dm * INNERD];
__device__ __nv_bfloat16 g_wT_fcp_lo [Dm * INNERD];

// --------------------------- PTX helpers -----------------------------------
__device__ __forceinline__ uint32_t smem_u32(const void* p) {
    uint32_t a;
    asm("{ .reg .u64 t; cvta.to.shared.u64 t, %1; cvt.u32.u64 %0, t; }"
        : "=r"(a) : "l"(p));
    return a;
}

__device__ __forceinline__ void cpasync16(uint32_t dst, const void* src) {
    asm volatile("cp.async.cg.shared.global [%0], [%1], 16;"
                 :: "r"(dst), "l"(src));
}
__device__ __forceinline__ void cp_commit() {
    asm volatile("cp.async.commit_group;" ::: "memory");
}
__device__ __forceinline__ void cp_wait1() {
    asm volatile("cp.async.wait_group 1;" ::: "memory");
}

#define LDSM4(r0, r1, r2, r3, addr) \
    asm volatile("ldmatrix.sync.aligned.m8n8.x4.shared.b16 {%0,%1,%2,%3}, [%4];" \
                 : "=r"(r0), "=r"(r1), "=r"(r2), "=r"(r3) : "r"(addr))

#define LDSM4T(r0, r1, r2, r3, addr) \
    asm volatile("ldmatrix.sync.aligned.m8n8.x4.trans.shared.b16 {%0,%1,%2,%3}, [%4];" \
                 : "=r"(r0), "=r"(r1), "=r"(r2), "=r"(r3) : "r"(addr))

__device__ __forceinline__ void mma16816(float* d, const uint32_t* a,
                                         const uint32_t* b) {
    asm volatile(
        "mma.sync.aligned.m16n8k16.row.col.f32.bf16.bf16.f32 "
        "{%0,%1,%2,%3}, {%4,%5,%6,%7}, {%8,%9}, {%0,%1,%2,%3};"
        : "+f"(d[0]), "+f"(d[1]), "+f"(d[2]), "+f"(d[3])
        : "r"(a[0]), "r"(a[1]), "r"(a[2]), "r"(a[3]), "r"(b[0]), "r"(b[1]));
}

// ---------------------------------------------------------------------------
// Weight prep: W[K,N] fp32 -> T[N,K] bf16 hi + lo (transpose + split)
// ---------------------------------------------------------------------------
__global__ void wprep(const float* __restrict__ W,
                      __nv_bfloat16* __restrict__ Thi,
                      __nv_bfloat16* __restrict__ Tlo, int K, int N)
{
    __shared__ float t[32][33];
    const int n0 = blockIdx.x * 32, k0 = blockIdx.y * 32;
    const int tx = threadIdx.x, ty = threadIdx.y;
    #pragma unroll
    for (int i = 0; i < 4; ++i)
        t[ty + i * 8][tx] = W[(size_t)(k0 + ty + i * 8) * N + n0 + tx];
    __syncthreads();
    #pragma unroll
    for (int i = 0; i < 4; ++i) {
        const float f = t[tx][ty + i * 8];
        const __nv_bfloat16 hi = __float2bfloat16(f);
        const float lo = f - __bfloat162float(hi);
        const size_t o = (size_t)(n0 + ty + i * 8) * K + k0 + tx;
        Thi[o] = hi;
        Tlo[o] = __float2bfloat16(lo);
    }
}

// ---------------------------------------------------------------------------
// LayerNorm producing bf16 hi/lo split
// ---------------------------------------------------------------------------
__global__ void layernorm_hilo(const float* __restrict__ x,
                               const float* __restrict__ g,
                               const float* __restrict__ b,
                               __nv_bfloat16* __restrict__ yhi,
                               __nv_bfloat16* __restrict__ ylo)
{
    __shared__ float red[16];
    const int row = blockIdx.x;
    const float* xr = x + (size_t)row * Dm;
    const int t = threadIdx.x;

    float v0 = xr[t], v1 = xr[t + 256], v2 = xr[t + 512];
    float s  = v0 + v1 + v2;
    float s2 = v0 * v0 + v1 * v1 + v2 * v2;

    #pragma unroll
    for (int o = 16; o >= 1; o >>= 1) {
        s  += __shfl_xor_sync(0xffffffffu, s,  o);
        s2 += __shfl_xor_sync(0xffffffffu, s2, o);
    }
    const int warp = t >> 5, lane = t & 31;
    if (lane == 0) { red[warp] = s; red[8 + warp] = s2; }
    __syncthreads();
    if (warp == 0) {
        float a  = (lane < 8) ? red[lane] : 0.0f;
        float a2 = (lane < 8) ? red[8 + lane] : 0.0f;
        #pragma unroll
        for (int o = 4; o >= 1; o >>= 1) {
            a  += __shfl_xor_sync(0xffffffffu, a,  o);
            a2 += __shfl_xor_sync(0xffffffffu, a2, o);
        }
        if (lane == 0) { red[0] = a; red[1] = a2; }
    }
    __syncthreads();
    const float mean = red[0] * (1.0f / Dm);
    const float var  = red[1] * (1.0f / Dm) - mean * mean;
    const float rstd = rsqrtf(var + 1e-5f);

    const size_t rb = (size_t)row * Dm;
    #pragma unroll
    for (int i = 0; i < 3; ++i) {
        const int c = t + i * 256;
        const float v = (i == 0) ? v0 : (i == 1) ? v1 : v2;
        const float f = (v - mean) * rstd * g[c] + b[c];
        const __nv_bfloat16 hi = __float2bfloat16(f);
        yhi[rb + c] = hi;
        ylo[rb + c] = __float2bfloat16(f - __bfloat162float(hi));
    }
}

// ---------------------------------------------------------------------------
// mma.sync GEMM (as R7). EPI 2: fp32 + bias + residual;
// EPI 3: bias + GELU -> bf16 hi/lo; EPI 4: bias (+0.125 scale on cols<768)
// -> bf16 hi/lo (QKV producer).
// ---------------------------------------------------------------------------
__device__ __forceinline__ float gelu_exact(float x) {
    return 0.5f * x * (1.0f + erff(x * 0.70710678118654752f));
}

#define ROWB      80
#define ARRB      (128 * ROWB)
#define BUFB      (4 * ARRB)
#define NSTAGE    3
#define GSMEM_SIZE (NSTAGE * BUFB)

template <int EPI>
__global__ __launch_bounds__(256)
void gemm_mma(const __nv_bfloat16* __restrict__ Ahi, const __nv_bfloat16* __restrict__ Alo,
              const __nv_bfloat16* __restrict__ Bhi, const __nv_bfloat16* __restrict__ Blo,
              const float* __restrict__ bias, const float* __restrict__ res,
              float* __restrict__ C,
              __nv_bfloat16* __restrict__ Chi, __nv_bfloat16* __restrict__ Clo,
              int M, int N, int K)
{
    extern __shared__ char smem[];
    const uint32_t sbase = smem_u32(smem);
    const int tid  = threadIdx.x;
    const int wid  = tid >> 5;
    const int lane = tid & 31;
    const int brow = blockIdx.y * 128;
    const int bcol = blockIdx.x * 128;

    const int arr  = tid >> 6;
    const int u    = tid & 63;
    const int rowb = u >> 2;
    const int chk  = u & 3;
    const __nv_bfloat16* gsel =
        (arr == 0) ? Ahi : (arr == 1) ? Alo : (arr == 2) ? Bhi : Blo;
    const int gbase_row = (arr < 2) ? brow : bcol;
    const char* gsrc = (const char*)(gsel + (size_t)(gbase_row + rowb) * K) + chk * 16;
    const uint32_t sdst0 = sbase + arr * ARRB + rowb * ROWB + chk * 16;
    const size_t grow16 = (size_t)16 * K * 2;

    const int NC = K >> 5;

    const int m0 = (wid >> 2) * 64;
    const int n0 = (wid & 3) * 32;
    const int a_r = (lane & 7) + ((lane >> 3) & 1) * 8;
    const int a_k = ((lane >> 4) & 1) * 16;
    const int b_r = (lane & 7) + ((lane >> 4) & 1) * 8;
    const int b_k = ((lane >> 3) & 1) * 16;
    const uint32_t aoff = (uint32_t)((m0 + a_r) * ROWB + a_k);
    const uint32_t boff = (uint32_t)((n0 + b_r) * ROWB + b_k);

    float d[4][4][4];
    #pragma unroll
    for (int mi = 0; mi < 4; ++mi)
        #pragma unroll
        for (int ni = 0; ni < 4; ++ni)
            #pragma unroll
            for (int q = 0; q < 4; ++q) d[mi][ni][q] = 0.0f;

    #pragma unroll
    for (int c = 0; c < 2; ++c) {
        const uint32_t sd = sdst0 + (uint32_t)c * BUFB;
        const char* gs = gsrc + (size_t)c * 64;
        #pragma unroll
        for (int j = 0; j < 8; ++j)
            cpasync16(sd + j * (16 * ROWB), gs + j * grow16);
        cp_commit();
    }

    for (int c = 0; c < NC; ++c) {
        cp_wait1();
        __syncthreads();

        if (c + 2 < NC) {
            const uint32_t sd = sdst0 + (uint32_t)((c + 2) % NSTAGE) * BUFB;
            const char* gs = gsrc + (size_t)(c + 2) * 64;
            #pragma unroll
            for (int j = 0; j < 8; ++j)
                cpasync16(sd + j * (16 * ROWB), gs + j * grow16);
        }
        cp_commit();

        const uint32_t bufb = sbase + (uint32_t)(c % NSTAGE) * BUFB;
        #pragma unroll
        for (int ks = 0; ks < 2; ++ks) {
            const uint32_t kb = ks * 32;
            uint32_t ah[4][4], al[4][4], bh[4][2], bl[4][2];
            #pragma unroll
            for (int mi = 0; mi < 4; ++mi) {
                LDSM4(ah[mi][0], ah[mi][1], ah[mi][2], ah[mi][3],
                      bufb + aoff + mi * (16 * ROWB) + kb);
                LDSM4(al[mi][0], al[mi][1], al[mi][2], al[mi][3],
                      bufb + ARRB + aoff + mi * (16 * ROWB) + kb);
            }
            #pragma unroll
            for (int nj = 0; nj < 2; ++nj) {
                LDSM4(bh[nj * 2][0], bh[nj * 2][1], bh[nj * 2 + 1][0], bh[nj * 2 + 1][1],
                      bufb + 2 * ARRB + boff + nj * (16 * ROWB) + kb);
                LDSM4(bl[nj * 2][0], bl[nj * 2][1], bl[nj * 2 + 1][0], bl[nj * 2 + 1][1],
                      bufb + 3 * ARRB + boff + nj * (16 * ROWB) + kb);
            }
            #pragma unroll
            for (int mi = 0; mi < 4; ++mi)
                #pragma unroll
                for (int ni = 0; ni < 4; ++ni) {
                    mma16816(d[mi][ni], ah[mi], bh[ni]);
                    mma16816(d[mi][ni], ah[mi], bl[ni]);
                    mma16816(d[mi][ni], al[mi], bh[ni]);
                }
        }
    }

    const int tr = lane >> 2;
    const int tc = (lane & 3) * 2;
    #pragma unroll
    for (int mi = 0; mi < 4; ++mi) {
        #pragma unroll
        for (int half = 0; half < 2; ++half) {
            const int row = brow + m0 + mi * 16 + tr + half * 8;
            #pragma unroll
            for (int ni = 0; ni < 4; ++ni) {
                const int col = bcol + n0 + ni * 8 + tc;
                const float2 bv = *(const float2*)(bias + col);
                float v0 = d[mi][ni][half * 2 + 0] + bv.x;
                float v1 = d[mi][ni][half * 2 + 1] + bv.y;
                if (EPI == 2) {
                    const float2 rv = *(const float2*)(res + (size_t)row * N + col);
                    v0 += rv.x; v1 += rv.y;
                    *(float2*)(C + (size_t)row * N + col) = make_float2(v0, v1);
                }
                if (EPI == 3) {
                    const float gq0 = gelu_exact(v0);
                    const float gq1 = gelu_exact(v1);
                    const __nv_bfloat162 h2 = __floats2bfloat162_rn(gq0, gq1);
                    const __nv_bfloat162 l2 = __floats2bfloat162_rn(
                        gq0 - __low2float(h2), gq1 - __high2float(h2));
                    *(__nv_bfloat162*)(Chi + (size_t)row * N + col) = h2;
                    *(__nv_bfloat162*)(Clo + (size_t)row * N + col) = l2;
                }
                if (EPI == 4) {
                    const float s4 = (col < 768) ? 0.125f : 1.0f;
                    const float q0 = v0 * s4, q1 = v1 * s4;
                    const __nv_bfloat162 h2 = __floats2bfloat162_rn(q0, q1);
                    const __nv_bfloat162 l2 = __floats2bfloat162_rn(
                        q0 - __low2float(h2), q1 - __high2float(h2));
                    *(__nv_bfloat162*)(Chi + (size_t)row * N + col) = h2;
                    *(__nv_bfloat162*)(Clo + (size_t)row * N + col) = l2;
                }
            }
        }
    }
}

// ---------------------------------------------------------------------------
// Flash attention via mma.sync bf16 3-split. Q tile 128 rows, K chunks of 64.
// 8 warps, warp w owns Q rows [w*16, w*16+16). Double-buffered K/V cp.async.
// Inputs: qkv hi/lo bf16 (Q pre-scaled by 0.125). Output: ctx hi/lo bf16.
// ---------------------------------------------------------------------------
#define FP    144                 // smem row pitch bytes (64 bf16 + 16B pad)
#define FQH   0
#define FQL   18432               // 128*144
#define FKV0  36864
#define KVARR 9216                // 64*144
#define KVBUF (4 * KVARR)         // Kh,Kl,Vh,Vl
#define FSMEM (FKV0 + 2 * KVBUF)  // 110592

__global__ __launch_bounds__(256)
void flash_mma(const __nv_bfloat16* __restrict__ qkvh,
               const __nv_bfloat16* __restrict__ qkvl,
               __nv_bfloat16* __restrict__ chi,
               __nv_bfloat16* __restrict__ clo)
{
    extern __shared__ char fs[];
    const uint32_t sb = smem_u32(fs);
    const int tid = threadIdx.x, wid = tid >> 5, lane = tid & 31;
    const int bb = blockIdx.y / NHEAD, hh = blockIdx.y % NHEAD;
    const int qt = blockIdx.x;
    const int NC = 2 * qt + 2;

    const size_t bbase = (size_t)bb * SEQ * D3;

    // ---- stage Q (group 0) ----
    {
        const int aq = tid >> 7;            // 0 hi, 1 lo
        const int uq = tid & 127;
        const int qc = uq & 7, qr = uq >> 3;
        const __nv_bfloat16* qsrc = (aq ? qkvl : qkvh) + bbase
            + (size_t)(qt * 128 + qr) * D3 + hh * 64 + qc * 8;
        const uint32_t qdst = sb + (aq ? FQL : FQH) + qr * FP + qc * 16;
        #pragma unroll
        for (int i = 0; i < 8; ++i)
            cpasync16(qdst + i * 16 * FP, qsrc + (size_t)i * 16 * D3);
        cp_commit();
    }

    // ---- K/V staging pointers ----
    const int arr = tid >> 6;               // 0 Kh 1 Kl 2 Vh 3 Vl
    const int u = tid & 63;
    const int c = u & 7, r = u >> 3;
    const __nv_bfloat16* kvsrc0 = ((arr & 1) ? qkvl : qkvh) + bbase
        + (size_t)r * D3 + ((arr < 2) ? 768 : 1536) + hh * 64 + c * 8;
    const uint32_t kvdst0 = sb + FKV0 + arr * KVARR + r * FP + c * 16;

    // stage chunk 0 (group 1)
    #pragma unroll
    for (int i = 0; i < 8; ++i)
        cpasync16(kvdst0 + i * 8 * FP, kvsrc0 + (size_t)i * 8 * D3);
    cp_commit();

    // ---- per-warp state ----
    uint32_t qfh[4][4], qfl[4][4];
    float o[8][4];
    float mrow[2] = {-1e30f, -1e30f};
    float lrow[2] = {0.0f, 0.0f};
    #pragma unroll
    for (int j = 0; j < 8; ++j)
        #pragma unroll
        for (int q = 0; q < 4; ++q) o[j][q] = 0.0f;

    const uint32_t qlda = (uint32_t)((wid * 16 + (lane & 7) + 8 * ((lane >> 3) & 1)) * FP
                                     + ((lane >> 4) & 1) * 16);
    const int tr = lane >> 2;
    const int tc = (lane & 3) * 2;

    for (int kt = 0; kt < NC; ++kt) {
        if (kt + 1 < NC) {
            const __nv_bfloat16* s = kvsrc0 + (size_t)(kt + 1) * 64 * D3;
            const uint32_t d0 = kvdst0 + (((kt + 1) & 1) ? KVBUF : 0u);
            #pragma unroll
            for (int i = 0; i < 8; ++i)
                cpasync16(d0 + i * 8 * FP, s + (size_t)i * 8 * D3);
        }
        cp_commit();
        cp_wait1();
        __syncthreads();

        if (kt == 0) {
            #pragma unroll
            for (int s = 0; s < 4; ++s) {
                LDSM4(qfh[s][0], qfh[s][1], qfh[s][2], qfh[s][3],
                      sb + FQH + qlda + s * 32);
                LDSM4(qfl[s][0], qfl[s][1], qfl[s][2], qfl[s][3],
                      sb + FQL + qlda + s * 32);
            }
        }

        const uint32_t kbuf = sb + FKV0 + (uint32_t)((kt & 1) ? KVBUF : 0u);

        // ---- S = Q K^T (3-split) ----
        float sacc[8][4];
        #pragma unroll
        for (int j = 0; j < 8; ++j)
            #pragma unroll
            for (int q = 0; q < 4; ++q) sacc[j][q] = 0.0f;

        #pragma unroll
        for (int j = 0; j < 8; ++j) {
            uint32_t bhf[4][2], blf[4][2];
            const uint32_t ka = kbuf + (j * 8 + (lane & 7)) * FP + ((lane >> 3) & 3) * 16;
            LDSM4(bhf[0][0], bhf[0][1], bhf[1][0], bhf[1][1], ka);
            LDSM4(bhf[2][0], bhf[2][1], bhf[3][0], bhf[3][1], ka + 64);
            LDSM4(blf[0][0], blf[0][1], blf[1][0], blf[1][1], ka + KVARR);
            LDSM4(blf[2][0], blf[2][1], blf[3][0], blf[3][1], ka + KVARR + 64);
            #pragma unroll
            for (int s = 0; s < 4; ++s) {
                mma16816(sacc[j], qfh[s], bhf[s]);
                mma16816(sacc[j], qfh[s], blf[s]);
                mma16816(sacc[j], qfl[s], bhf[s]);
            }
        }

        // ---- causal mask (diagonal chunks only) ----
        if (kt >= 2 * qt) {
            const int row0 = qt * 128 + wid * 16 + tr;
            const int col0 = kt * 64 + tc;
            #pragma unroll
            for (int j = 0; j < 8; ++j) {
                const int cj = col0 + j * 8;
                if (cj     > row0)     sacc[j][0] = -1e30f;
                if (cj + 1 > row0)     sacc[j][1] = -1e30f;
                if (cj     > row0 + 8) sacc[j][2] = -1e30f;
                if (cj + 1 > row0 + 8) sacc[j][3] = -1e30f;
            }
        }

        // ---- online softmax (rows spread over lane quads) ----
        #pragma unroll
        for (int rr = 0; rr < 2; ++rr) {
            float mc = -1e30f;
            #pragma unroll
            for (int j = 0; j < 8; ++j)
                mc = fmaxf(mc, fmaxf(sacc[j][2 * rr], sacc[j][2 * rr + 1]));
            mc = fmaxf(mc, __shfl_xor_sync(0xffffffffu, mc, 1));
            mc = fmaxf(mc, __shfl_xor_sync(0xffffffffu, mc, 2));
            const float mn = fmaxf(mrow[rr], mc);
            const float alpha = __expf(mrow[rr] - mn);
            float ssum = 0.0f;
            #pragma unroll
            for (int j = 0; j < 8; ++j) {
                const float p0 = __expf(sacc[j][2 * rr]     - mn);
                const float p1 = __expf(sacc[j][2 * rr + 1] - mn);
                sacc[j][2 * rr] = p0; sacc[j][2 * rr + 1] = p1;
                ssum += p0 + p1;
            }
            ssum += __shfl_xor_sync(0xffffffffu, ssum, 1);
            ssum += __shfl_xor_sync(0xffffffffu, ssum, 2);
            lrow[rr] = lrow[rr] * alpha + ssum;
            mrow[rr] = mn;
            #pragma unroll
            for (int j = 0; j < 8; ++j) {
                o[j][2 * rr]     *= alpha;
                o[j][2 * rr + 1] *= alpha;
            }
        }

        // ---- pack P into A-fragments (hi + lo) ----
        uint32_t pah[4][4], pal[4][4];
        #pragma unroll
        for (int t = 0; t < 4; ++t) {
            #pragma unroll
            for (int hj = 0; hj < 2; ++hj) {
                const int j = 2 * t + hj;
                const __nv_bfloat162 x01 = __floats2bfloat162_rn(sacc[j][0], sacc[j][1]);
                const __nv_bfloat162 x23 = __floats2bfloat162_rn(sacc[j][2], sacc[j][3]);
                const __nv_bfloat162 y01 = __floats2bfloat162_rn(
                    sacc[j][0] - __low2float(x01), sacc[j][1] - __high2float(x01));
                const __nv_bfloat162 y23 = __floats2bfloat162_rn(
                    sacc[j][2] - __low2float(x23), sacc[j][3] - __high2float(x23));
                pah[t][2 * hj]     = *(const uint32_t*)&x01;
                pah[t][2 * hj + 1] = *(const uint32_t*)&x23;
                pal[t][2 * hj]     = *(const uint32_t*)&y01;
                pal[t][2 * hj + 1] = *(const uint32_t*)&y23;
            }
        }

        // ---- O += P V (3-split; V fragments via ldmatrix.trans) ----
        #pragma unroll
        for (int t = 0; t < 4; ++t) {
            #pragma unroll
            for (int jp = 0; jp < 4; ++jp) {
                const uint32_t va = kbuf + 2 * KVARR
                    + (t * 16 + (lane & 7) + ((lane >> 3) & 1) * 8) * FP
                    + jp * 32 + ((lane >> 4) & 1) * 16;
                uint32_t vh[4], vl[4];
                LDSM4T(vh[0], vh[1], vh[2], vh[3], va);
                LDSM4T(vl[0], vl[1], vl[2], vl[3], va + KVARR);
                mma16816(o[2 * jp],     pah[t], vh);
                mma16816(o[2 * jp],     pah[t], vl);
                mma16816(o[2 * jp],     pal[t], vh);
                mma16816(o[2 * jp + 1], pah[t], vh + 2);
                mma16816(o[2 * jp + 1], pah[t], vl + 2);
                mma16816(o[2 * jp + 1], pal[t], vh + 2);
            }
        }

        __syncthreads();
    }

    // ---- epilogue: normalize, split hi/lo, write ctx ----
    const float i0 = 1.0f / lrow[0];
    const float i1 = 1.0f / lrow[1];
    const int row0 = qt * 128 + wid * 16 + tr;
    const size_t g0 = ((size_t)(bb * SEQ) + row0) * Dm + hh * 64 + tc;
    #pragma unroll
    for (int j = 0; j < 8; ++j) {
        const float a0 = o[j][0] * i0, a1 = o[j][1] * i0;
        const float a2 = o[j][2] * i1, a3 = o[j][3] * i1;
        const __nv_bfloat162 h01 = __floats2bfloat162_rn(a0, a1);
        const __nv_bfloat162 l01 = __floats2bfloat162_rn(
            a0 - __low2float(h01), a1 - __high2float(h01));
        const __nv_bfloat162 h23 = __floats2bfloat162_rn(a2, a3);
        const __nv_bfloat162 l23 = __floats2bfloat162_rn(
            a2 - __low2float(h23), a3 - __high2float(h23));
        *(__nv_bfloat162*)(chi + g0 + j * 8)          = h01;
        *(__nv_bfloat162*)(clo + g0 + j * 8)          = l01;
        *(__nv_bfloat162*)(chi + g0 + 8 * Dm + j * 8) = h23;
        *(__nv_bfloat162*)(clo + g0 + 8 * Dm + j * 8) = l23;
    }
}

// ---------------------------------------------------------------------------
// Launch
// ---------------------------------------------------------------------------
extern "C" void kernel_launch(void* const* d_in, const int* in_sizes, int n_in,
                              void* d_out, int out_size)
{
    const float* hidden    = (const float*)d_in[0];
    const float* ln1_g     = (const float*)d_in[2];
    const float* ln1_b     = (const float*)d_in[3];
    const float* w_attn    = (const float*)d_in[4];
    const float* b_attn    = (const float*)d_in[5];
    const float* w_cproj   = (const float*)d_in[6];
    const float* b_cproj   = (const float*)d_in[7];
    const float* ln2_g     = (const float*)d_in[8];
    const float* ln2_b     = (const float*)d_in[9];
    const float* w_fc      = (const float*)d_in[10];
    const float* b_fc      = (const float*)d_in[11];
    const float* w_fc_proj = (const float*)d_in[12];
    const float* b_fc_proj = (const float*)d_in[13];
    float* out = (float*)d_out;

    float* h;
    __nv_bfloat16 *qvh, *qvl, *xh, *xl, *ch, *cl, *yh, *yl, *ah, *al;
    __nv_bfloat16 *wah, *wal, *wch, *wcl, *wfh, *wfl, *wph, *wpl;
    cudaGetSymbolAddress((void**)&h,   g_h);
    cudaGetSymbolAddress((void**)&qvh, g_qkv_hi);  cudaGetSymbolAddress((void**)&qvl, g_qkv_lo);
    cudaGetSymbolAddress((void**)&xh, g_xln_hi);   cudaGetSymbolAddress((void**)&xl, g_xln_lo);
    cudaGetSymbolAddress((void**)&ch, g_ctx_hi);   cudaGetSymbolAddress((void**)&cl, g_ctx_lo);
    cudaGetSymbolAddress((void**)&yh, g_yln_hi);   cudaGetSymbolAddress((void**)&yl, g_yln_lo);
    cudaGetSymbolAddress((void**)&ah, g_act_hi);   cudaGetSymbolAddress((void**)&al, g_act_lo);
    cudaGetSymbolAddress((void**)&wah, g_wT_attn_hi); cudaGetSymbolAddress((void**)&wal, g_wT_attn_lo);
    cudaGetSymbolAddress((void**)&wch, g_wT_cprj_hi); cudaGetSymbolAddress((void**)&wcl, g_wT_cprj_lo);
    cudaGetSymbolAddress((void**)&wfh, g_wT_fc_hi);   cudaGetSymbolAddress((void**)&wfl, g_wT_fc_lo);
    cudaGetSymbolAddress((void**)&wph, g_wT_fcp_hi);  cudaGetSymbolAddress((void**)&wpl, g_wT_fcp_lo);

    cudaFuncSetAttribute(gemm_mma<2>, cudaFuncAttributeMaxDynamicSharedMemorySize, GSMEM_SIZE);
    cudaFuncSetAttribute(gemm_mma<3>, cudaFuncAttributeMaxDynamicSharedMemorySize, GSMEM_SIZE);
    cudaFuncSetAttribute(gemm_mma<4>, cudaFuncAttributeMaxDynamicSharedMemorySize, GSMEM_SIZE);
    cudaFuncSetAttribute(flash_mma,   cudaFuncAttributeMaxDynamicSharedMemorySize, FSMEM);

    const dim3 tb(32, 8);
    wprep<<<dim3(D3 / 32,     Dm / 32),     tb>>>(w_attn,    wah, wal, Dm,     D3);
    wprep<<<dim3(Dm / 32,     Dm / 32),     tb>>>(w_cproj,   wch, wcl, Dm,     Dm);
    wprep<<<dim3(INNERD / 32, Dm / 32),     tb>>>(w_fc,      wfh, wfl, Dm,     INNERD);
    wprep<<<dim3(Dm / 32,     INNERD / 32), tb>>>(w_fc_proj, wph, wpl, INNERD, Dm);

    // 1. LN1 -> bf16 hi/lo
    layernorm_hilo<<<Mrows, 256>>>(hidden, ln1_g, ln1_b, xh, xl);
    // 2. QKV projection -> bf16 hi/lo (Q pre-scaled)
    gemm_mma<4><<<dim3(D3 / 128, Mrows / 128), 256, GSMEM_SIZE>>>(
        xh, xl, wah, wal, b_attn, nullptr, nullptr, qvh, qvl, Mrows, D3, Dm);
    // 3. Flash attention (mma) -> ctx hi/lo
    flash_mma<<<dim3(SEQ / 128, BATCH * NHEAD), 256, FSMEM>>>(qvh, qvl, ch, cl);
    // 4. cproj + residual -> h (fp32)
    gemm_mma<2><<<dim3(Dm / 128, Mrows / 128), 256, GSMEM_SIZE>>>(
        ch, cl, wch, wcl, b_cproj, hidden, h, nullptr, nullptr, Mrows, Dm, Dm);
    // 5. LN2 -> yln hi/lo
    layernorm_hilo<<<Mrows, 256>>>(h, ln2_g, ln2_b, yh, yl);
    // 6. fc + GELU -> act hi/lo
    gemm_mma<3><<<dim3(INNERD / 128, Mrows / 128), 256, GSMEM_SIZE>>>(
        yh, yl, wfh, wfl, b_fc, nullptr, nullptr, ah, al, Mrows, INNERD, Dm);
    // 7. fc_proj + residual -> out
    gemm_mma<2><<<dim3(Dm / 128, Mrows / 128), 256, GSMEM_SIZE>>>(
        ah, al, wph, wpl, b_fc_proj, h, out, nullptr, nullptr, Mrows, Dm, INNERD);
}

// round 11
// speedup vs baseline: 3.0752x; 1.5930x over previous
#include <cuda_runtime.h>
#include <cuda_bf16.h>
#include <cstdint>

// ---------------------------------------------------------------------------
// GPT-2 block. B=2, S=4096, D=768, H=12, HD=64, INNER=3072. M = B*S = 8192.
// GEMMs + flash attention all via mma.sync bf16 (3-split hi/lo, fp32 accum).
// Flash: 64-q tiles, 128 threads, 2 CTAs/SM, longest-first scheduling.
// ---------------------------------------------------------------------------

#define Mrows  8192
#define Dm     768
#define D3     2304
#define INNERD 3072
#define NHEAD  12
#define HD     64
#define SEQ    4096
#define BATCH  2

// ------------------------------- scratch -----------------------------------
__device__ float g_h[Mrows * Dm];

__device__ __nv_bfloat16 g_qkv_hi[Mrows * D3];
__device__ __nv_bfloat16 g_qkv_lo[Mrows * D3];
__device__ __nv_bfloat16 g_xln_hi[Mrows * Dm];
__device__ __nv_bfloat16 g_xln_lo[Mrows * Dm];
__device__ __nv_bfloat16 g_ctx_hi[Mrows * Dm];
__device__ __nv_bfloat16 g_ctx_lo[Mrows * Dm];
__device__ __nv_bfloat16 g_yln_hi[Mrows * Dm];
__device__ __nv_bfloat16 g_yln_lo[Mrows * Dm];
__device__ __nv_bfloat16 g_act_hi[Mrows * INNERD];
__device__ __nv_bfloat16 g_act_lo[Mrows * INNERD];

__device__ __nv_bfloat16 g_wT_attn_hi[D3 * Dm];
__device__ __nv_bfloat16 g_wT_attn_lo[D3 * Dm];
__device__ __nv_bfloat16 g_wT_cprj_hi[Dm * Dm];
__device__ __nv_bfloat16 g_wT_cprj_lo[Dm * Dm];
__device__ __nv_bfloat16 g_wT_fc_hi  [INNERD * Dm];
__device__ __nv_bfloat16 g_wT_fc_lo  [INNERD * Dm];
__device__ __nv_bfloat16 g_wT_fcp_hi [Dm * INNERD];
__device__ __nv_bfloat16 g_wT_fcp_lo [Dm * INNERD];

// --------------------------- PTX helpers -----------------------------------
__device__ __forceinline__ uint32_t smem_u32(const void* p) {
    uint32_t a;
    asm("{ .reg .u64 t; cvta.to.shared.u64 t, %1; cvt.u32.u64 %0, t; }"
        : "=r"(a) : "l"(p));
    return a;
}

__device__ __forceinline__ void cpasync16(uint32_t dst, const void* src) {
    asm volatile("cp.async.cg.shared.global [%0], [%1], 16;"
                 :: "r"(dst), "l"(src));
}
__device__ __forceinline__ void cp_commit() {
    asm volatile("cp.async.commit_group;" ::: "memory");
}
__device__ __forceinline__ void cp_wait1() {
    asm volatile("cp.async.wait_group 1;" ::: "memory");
}

#define LDSM4(r0, r1, r2, r3, addr) \
    asm volatile("ldmatrix.sync.aligned.m8n8.x4.shared.b16 {%0,%1,%2,%3}, [%4];" \
                 : "=r"(r0), "=r"(r1), "=r"(r2), "=r"(r3) : "r"(addr))

#define LDSM4T(r0, r1, r2, r3, addr) \
    asm volatile("ldmatrix.sync.aligned.m8n8.x4.trans.shared.b16 {%0,%1,%2,%3}, [%4];" \
                 : "=r"(r0), "=r"(r1), "=r"(r2), "=r"(r3) : "r"(addr))

__device__ __forceinline__ void mma16816(float* d, const uint32_t* a,
                                         const uint32_t* b) {
    asm volatile(
        "mma.sync.aligned.m16n8k16.row.col.f32.bf16.bf16.f32 "
        "{%0,%1,%2,%3}, {%4,%5,%6,%7}, {%8,%9}, {%0,%1,%2,%3};"
        : "+f"(d[0]), "+f"(d[1]), "+f"(d[2]), "+f"(d[3])
        : "r"(a[0]), "r"(a[1]), "r"(a[2]), "r"(a[3]), "r"(b[0]), "r"(b[1]));
}

// ---------------------------------------------------------------------------
// Weight prep: W[K,N] fp32 -> T[N,K] bf16 hi + lo (transpose + split)
// ---------------------------------------------------------------------------
__global__ void wprep(const float* __restrict__ W,
                      __nv_bfloat16* __restrict__ Thi,
                      __nv_bfloat16* __restrict__ Tlo, int K, int N)
{
    __shared__ float t[32][33];
    const int n0 = blockIdx.x * 32, k0 = blockIdx.y * 32;
    const int tx = threadIdx.x, ty = threadIdx.y;
    #pragma unroll
    for (int i = 0; i < 4; ++i)
        t[ty + i * 8][tx] = W[(size_t)(k0 + ty + i * 8) * N + n0 + tx];
    __syncthreads();
    #pragma unroll
    for (int i = 0; i < 4; ++i) {
        const float f = t[tx][ty + i * 8];
        const __nv_bfloat16 hi = __float2bfloat16(f);
        const float lo = f - __bfloat162float(hi);
        const size_t o = (size_t)(n0 + ty + i * 8) * K + k0 + tx;
        Thi[o] = hi;
        Tlo[o] = __float2bfloat16(lo);
    }
}

// ---------------------------------------------------------------------------
// LayerNorm producing bf16 hi/lo split
// ---------------------------------------------------------------------------
__global__ void layernorm_hilo(const float* __restrict__ x,
                               const float* __restrict__ g,
                               const float* __restrict__ b,
                               __nv_bfloat16* __restrict__ yhi,
                               __nv_bfloat16* __restrict__ ylo)
{
    __shared__ float red[16];
    const int row = blockIdx.x;
    const float* xr = x + (size_t)row * Dm;
    const int t = threadIdx.x;

    float v0 = xr[t], v1 = xr[t + 256], v2 = xr[t + 512];
    float s  = v0 + v1 + v2;
    float s2 = v0 * v0 + v1 * v1 + v2 * v2;

    #pragma unroll
    for (int o = 16; o >= 1; o >>= 1) {
        s  += __shfl_xor_sync(0xffffffffu, s,  o);
        s2 += __shfl_xor_sync(0xffffffffu, s2, o);
    }
    const int warp = t >> 5, lane = t & 31;
    if (lane == 0) { red[warp] = s; red[8 + warp] = s2; }
    __syncthreads();
    if (warp == 0) {
        float a  = (lane < 8) ? red[lane] : 0.0f;
        float a2 = (lane < 8) ? red[8 + lane] : 0.0f;
        #pragma unroll
        for (int o = 4; o >= 1; o >>= 1) {
            a  += __shfl_xor_sync(0xffffffffu, a,  o);
            a2 += __shfl_xor_sync(0xffffffffu, a2, o);
        }
        if (lane == 0) { red[0] = a; red[1] = a2; }
    }
    __syncthreads();
    const float mean = red[0] * (1.0f / Dm);
    const float var  = red[1] * (1.0f / Dm) - mean * mean;
    const float rstd = rsqrtf(var + 1e-5f);

    const size_t rb = (size_t)row * Dm;
    #pragma unroll
    for (int i = 0; i < 3; ++i) {
        const int c = t + i * 256;
        const float v = (i == 0) ? v0 : (i == 1) ? v1 : v2;
        const float f = (v - mean) * rstd * g[c] + b[c];
        const __nv_bfloat16 hi = __float2bfloat16(f);
        yhi[rb + c] = hi;
        ylo[rb + c] = __float2bfloat16(f - __bfloat162float(hi));
    }
}

// ---------------------------------------------------------------------------
// mma.sync GEMM (as R7). EPI 2: fp32 + bias + residual;
// EPI 3: bias + GELU -> bf16 hi/lo; EPI 4: bias (+0.125 scale on cols<768)
// -> bf16 hi/lo (QKV producer).
// ---------------------------------------------------------------------------
__device__ __forceinline__ float gelu_exact(float x) {
    return 0.5f * x * (1.0f + erff(x * 0.70710678118654752f));
}

#define ROWB      80
#define ARRB      (128 * ROWB)
#define BUFB      (4 * ARRB)
#define NSTAGE    3
#define GSMEM_SIZE (NSTAGE * BUFB)

template <int EPI>
__global__ __launch_bounds__(256)
void gemm_mma(const __nv_bfloat16* __restrict__ Ahi, const __nv_bfloat16* __restrict__ Alo,
              const __nv_bfloat16* __restrict__ Bhi, const __nv_bfloat16* __restrict__ Blo,
              const float* __restrict__ bias, const float* __restrict__ res,
              float* __restrict__ C,
              __nv_bfloat16* __restrict__ Chi, __nv_bfloat16* __restrict__ Clo,
              int M, int N, int K)
{
    extern __shared__ char smem[];
    const uint32_t sbase = smem_u32(smem);
    const int tid  = threadIdx.x;
    const int wid  = tid >> 5;
    const int lane = tid & 31;
    const int brow = blockIdx.y * 128;
    const int bcol = blockIdx.x * 128;

    const int arr  = tid >> 6;
    const int u    = tid & 63;
    const int rowb = u >> 2;
    const int chk  = u & 3;
    const __nv_bfloat16* gsel =
        (arr == 0) ? Ahi : (arr == 1) ? Alo : (arr == 2) ? Bhi : Blo;
    const int gbase_row = (arr < 2) ? brow : bcol;
    const char* gsrc = (const char*)(gsel + (size_t)(gbase_row + rowb) * K) + chk * 16;
    const uint32_t sdst0 = sbase + arr * ARRB + rowb * ROWB + chk * 16;
    const size_t grow16 = (size_t)16 * K * 2;

    const int NC = K >> 5;

    const int m0 = (wid >> 2) * 64;
    const int n0 = (wid & 3) * 32;
    const int a_r = (lane & 7) + ((lane >> 3) & 1) * 8;
    const int a_k = ((lane >> 4) & 1) * 16;
    const int b_r = (lane & 7) + ((lane >> 4) & 1) * 8;
    const int b_k = ((lane >> 3) & 1) * 16;
    const uint32_t aoff = (uint32_t)((m0 + a_r) * ROWB + a_k);
    const uint32_t boff = (uint32_t)((n0 + b_r) * ROWB + b_k);

    float d[4][4][4];
    #pragma unroll
    for (int mi = 0; mi < 4; ++mi)
        #pragma unroll
        for (int ni = 0; ni < 4; ++ni)
            #pragma unroll
            for (int q = 0; q < 4; ++q) d[mi][ni][q] = 0.0f;

    #pragma unroll
    for (int c = 0; c < 2; ++c) {
        const uint32_t sd = sdst0 + (uint32_t)c * BUFB;
        const char* gs = gsrc + (size_t)c * 64;
        #pragma unroll
        for (int j = 0; j < 8; ++j)
            cpasync16(sd + j * (16 * ROWB), gs + j * grow16);
        cp_commit();
    }

    for (int c = 0; c < NC; ++c) {
        cp_wait1();
        __syncthreads();

        if (c + 2 < NC) {
            const uint32_t sd = sdst0 + (uint32_t)((c + 2) % NSTAGE) * BUFB;
            const char* gs = gsrc + (size_t)(c + 2) * 64;
            #pragma unroll
            for (int j = 0; j < 8; ++j)
                cpasync16(sd + j * (16 * ROWB), gs + j * grow16);
        }
        cp_commit();

        const uint32_t bufb = sbase + (uint32_t)(c % NSTAGE) * BUFB;
        #pragma unroll
        for (int ks = 0; ks < 2; ++ks) {
            const uint32_t kb = ks * 32;
            uint32_t ah[4][4], al[4][4], bh[4][2], bl[4][2];
            #pragma unroll
            for (int mi = 0; mi < 4; ++mi) {
                LDSM4(ah[mi][0], ah[mi][1], ah[mi][2], ah[mi][3],
                      bufb + aoff + mi * (16 * ROWB) + kb);
                LDSM4(al[mi][0], al[mi][1], al[mi][2], al[mi][3],
                      bufb + ARRB + aoff + mi * (16 * ROWB) + kb);
            }
            #pragma unroll
            for (int nj = 0; nj < 2; ++nj) {
                LDSM4(bh[nj * 2][0], bh[nj * 2][1], bh[nj * 2 + 1][0], bh[nj * 2 + 1][1],
                      bufb + 2 * ARRB + boff + nj * (16 * ROWB) + kb);
                LDSM4(bl[nj * 2][0], bl[nj * 2][1], bl[nj * 2 + 1][0], bl[nj * 2 + 1][1],
                      bufb + 3 * ARRB + boff + nj * (16 * ROWB) + kb);
            }
            #pragma unroll
            for (int mi = 0; mi < 4; ++mi)
                #pragma unroll
                for (int ni = 0; ni < 4; ++ni) {
                    mma16816(d[mi][ni], ah[mi], bh[ni]);
                    mma16816(d[mi][ni], ah[mi], bl[ni]);
                    mma16816(d[mi][ni], al[mi], bh[ni]);
                }
        }
    }

    const int tr = lane >> 2;
    const int tc = (lane & 3) * 2;
    #pragma unroll
    for (int mi = 0; mi < 4; ++mi) {
        #pragma unroll
        for (int half = 0; half < 2; ++half) {
            const int row = brow + m0 + mi * 16 + tr + half * 8;
            #pragma unroll
            for (int ni = 0; ni < 4; ++ni) {
                const int col = bcol + n0 + ni * 8 + tc;
                const float2 bv = *(const float2*)(bias + col);
                float v0 = d[mi][ni][half * 2 + 0] + bv.x;
                float v1 = d[mi][ni][half * 2 + 1] + bv.y;
                if (EPI == 2) {
                    const float2 rv = *(const float2*)(res + (size_t)row * N + col);
                    v0 += rv.x; v1 += rv.y;
                    *(float2*)(C + (size_t)row * N + col) = make_float2(v0, v1);
                }
                if (EPI == 3) {
                    const float gq0 = gelu_exact(v0);
                    const float gq1 = gelu_exact(v1);
                    const __nv_bfloat162 h2 = __floats2bfloat162_rn(gq0, gq1);
                    const __nv_bfloat162 l2 = __floats2bfloat162_rn(
                        gq0 - __low2float(h2), gq1 - __high2float(h2));
                    *(__nv_bfloat162*)(Chi + (size_t)row * N + col) = h2;
                    *(__nv_bfloat162*)(Clo + (size_t)row * N + col) = l2;
                }
                if (EPI == 4) {
                    const float s4 = (col < 768) ? 0.125f : 1.0f;
                    const float q0 = v0 * s4, q1 = v1 * s4;
                    const __nv_bfloat162 h2 = __floats2bfloat162_rn(q0, q1);
                    const __nv_bfloat162 l2 = __floats2bfloat162_rn(
                        q0 - __low2float(h2), q1 - __high2float(h2));
                    *(__nv_bfloat162*)(Chi + (size_t)row * N + col) = h2;
                    *(__nv_bfloat162*)(Clo + (size_t)row * N + col) = l2;
                }
            }
        }
    }
}

// ---------------------------------------------------------------------------
// Flash attention via mma.sync bf16 3-split.
// 64-q tiles, 128 threads (4 warps x 16 rows), 2 CTAs/SM, longest-first.
// K chunks of 64, double-buffered cp.async K/V.
// ---------------------------------------------------------------------------
#define FP    144                 // smem row pitch bytes (64 bf16 + 16B pad)
#define FQH   0
#define FQL   9216                // 64*144
#define FKV0  18432
#define KVARR 9216                // 64*144
#define KVBUF (4 * KVARR)         // Kh,Kl,Vh,Vl
#define FSMEM (FKV0 + 2 * KVBUF)  // 92160

__global__ __launch_bounds__(128, 2)
void flash_mma(const __nv_bfloat16* __restrict__ qkvh,
               const __nv_bfloat16* __restrict__ qkvl,
               __nv_bfloat16* __restrict__ chi,
               __nv_bfloat16* __restrict__ clo)
{
    extern __shared__ char fs[];
    const uint32_t sb = smem_u32(fs);
    const int tid = threadIdx.x, wid = tid >> 5, lane = tid & 31;
    const int bb = blockIdx.y / NHEAD, hh = blockIdx.y % NHEAD;
    const int qt = (SEQ / 64 - 1) - blockIdx.x;   // longest-first
    const int NC = qt + 1;

    const size_t bbase = (size_t)bb * SEQ * D3;

    // ---- stage Q hi+lo (group 0): 64 rows x 128B each of hi/lo ----
    {
        const int qc = tid & 7, qr = tid >> 3;     // qr 0..15
        #pragma unroll
        for (int part = 0; part < 2; ++part) {
            const __nv_bfloat16* src = (part ? qkvl : qkvh) + bbase
                + (size_t)(qt * 64 + qr) * D3 + hh * 64 + qc * 8;
            const uint32_t dst = sb + (part ? FQL : FQH) + qr * FP + qc * 16;
            #pragma unroll
            for (int i = 0; i < 4; ++i)
                cpasync16(dst + i * 16 * FP, src + (size_t)i * 16 * D3);
        }
        cp_commit();
    }

    // ---- K/V staging pointers: 4 arrays x 32 threads ----
    const int arr = tid >> 5;               // 0 Kh 1 Kl 2 Vh 3 Vl
    const int u = tid & 31;
    const int c = u & 7, r = u >> 3;        // r 0..3
    const __nv_bfloat16* kvsrc0 = ((arr & 1) ? qkvl : qkvh) + bbase
        + (size_t)r * D3 + ((arr < 2) ? 768 : 1536) + hh * 64 + c * 8;
    const uint32_t kvdst0 = sb + FKV0 + arr * KVARR + r * FP + c * 16;

    // stage chunk 0 (group 1)
    #pragma unroll
    for (int i = 0; i < 16; ++i)
        cpasync16(kvdst0 + i * 4 * FP, kvsrc0 + (size_t)i * 4 * D3);
    cp_commit();

    // ---- per-warp state ----
    uint32_t qfh[4][4], qfl[4][4];
    float o[8][4];
    float mrow[2] = {-1e30f, -1e30f};
    float lrow[2] = {0.0f, 0.0f};
    #pragma unroll
    for (int j = 0; j < 8; ++j)
        #pragma unroll
        for (int q = 0; q < 4; ++q) o[j][q] = 0.0f;

    const uint32_t qlda = (uint32_t)((wid * 16 + (lane & 7) + 8 * ((lane >> 3) & 1)) * FP
                                     + ((lane >> 4) & 1) * 16);
    const int tr = lane >> 2;
    const int tc = (lane & 3) * 2;

    for (int kt = 0; kt < NC; ++kt) {
        if (kt + 1 < NC) {
            const __nv_bfloat16* s = kvsrc0 + (size_t)(kt + 1) * 64 * D3;
            const uint32_t d0 = kvdst0 + (((kt + 1) & 1) ? KVBUF : 0u);
            #pragma unroll
            for (int i = 0; i < 16; ++i)
                cpasync16(d0 + i * 4 * FP, s + (size_t)i * 4 * D3);
        }
        cp_commit();
        cp_wait1();
        __syncthreads();

        if (kt == 0) {
            #pragma unroll
            for (int s = 0; s < 4; ++s) {
                LDSM4(qfh[s][0], qfh[s][1], qfh[s][2], qfh[s][3],
                      sb + FQH + qlda + s * 32);
                LDSM4(qfl[s][0], qfl[s][1], qfl[s][2], qfl[s][3],
                      sb + FQL + qlda + s * 32);
            }
        }

        const uint32_t kbuf = sb + FKV0 + (uint32_t)((kt & 1) ? KVBUF : 0u);

        // ---- S = Q K^T (3-split) ----
        float sacc[8][4];
        #pragma unroll
        for (int j = 0; j < 8; ++j)
            #pragma unroll
            for (int q = 0; q < 4; ++q) sacc[j][q] = 0.0f;

        #pragma unroll
        for (int j = 0; j < 8; ++j) {
            uint32_t bhf[4][2], blf[4][2];
            const uint32_t ka = kbuf + (j * 8 + (lane & 7)) * FP + ((lane >> 3) & 3) * 16;
            LDSM4(bhf[0][0], bhf[0][1], bhf[1][0], bhf[1][1], ka);
            LDSM4(bhf[2][0], bhf[2][1], bhf[3][0], bhf[3][1], ka + 64);
            LDSM4(blf[0][0], blf[0][1], blf[1][0], blf[1][1], ka + KVARR);
            LDSM4(blf[2][0], blf[2][1], blf[3][0], blf[3][1], ka + KVARR + 64);
            #pragma unroll
            for (int s = 0; s < 4; ++s) {
                mma16816(sacc[j], qfh[s], bhf[s]);
                mma16816(sacc[j], qfh[s], blf[s]);
                mma16816(sacc[j], qfl[s], bhf[s]);
            }
        }

        // ---- causal mask (diagonal chunk only) ----
        if (kt == qt) {
            const int row0 = qt * 64 + wid * 16 + tr;
            const int col0 = kt * 64 + tc;
            #pragma unroll
            for (int j = 0; j < 8; ++j) {
                const int cj = col0 + j * 8;
                if (cj     > row0)     sacc[j][0] = -1e30f;
                if (cj + 1 > row0)     sacc[j][1] = -1e30f;
                if (cj     > row0 + 8) sacc[j][2] = -1e30f;
                if (cj + 1 > row0 + 8) sacc[j][3] = -1e30f;
            }
        }

        // ---- online softmax (rows spread over lane quads) ----
        #pragma unroll
        for (int rr = 0; rr < 2; ++rr) {
            float mc = -1e30f;
            #pragma unroll
            for (int j = 0; j < 8; ++j)
                mc = fmaxf(mc, fmaxf(sacc[j][2 * rr], sacc[j][2 * rr + 1]));
            mc = fmaxf(mc, __shfl_xor_sync(0xffffffffu, mc, 1));
            mc = fmaxf(mc, __shfl_xor_sync(0xffffffffu, mc, 2));
            const float mn = fmaxf(mrow[rr], mc);
            const float alpha = __expf(mrow[rr] - mn);
            float ssum = 0.0f;
            #pragma unroll
            for (int j = 0; j < 8; ++j) {
                const float p0 = __expf(sacc[j][2 * rr]     - mn);
                const float p1 = __expf(sacc[j][2 * rr + 1] - mn);
                sacc[j][2 * rr] = p0; sacc[j][2 * rr + 1] = p1;
                ssum += p0 + p1;
            }
            ssum += __shfl_xor_sync(0xffffffffu, ssum, 1);
            ssum += __shfl_xor_sync(0xffffffffu, ssum, 2);
            lrow[rr] = lrow[rr] * alpha + ssum;
            mrow[rr] = mn;
            #pragma unroll
            for (int j = 0; j < 8; ++j) {
                o[j][2 * rr]     *= alpha;
                o[j][2 * rr + 1] *= alpha;
            }
        }

        // ---- pack P into A-fragments (hi + lo) ----
        uint32_t pah[4][4], pal[4][4];
        #pragma unroll
        for (int t = 0; t < 4; ++t) {
            #pragma unroll
            for (int hj = 0; hj < 2; ++hj) {
                const int j = 2 * t + hj;
                const __nv_bfloat162 x01 = __floats2bfloat162_rn(sacc[j][0], sacc[j][1]);
                const __nv_bfloat162 x23 = __floats2bfloat162_rn(sacc[j][2], sacc[j][3]);
                const __nv_bfloat162 y01 = __floats2bfloat162_rn(
                    sacc[j][0] - __low2float(x01), sacc[j][1] - __high2float(x01));
                const __nv_bfloat162 y23 = __floats2bfloat162_rn(
                    sacc[j][2] - __low2float(x23), sacc[j][3] - __high2float(x23));
                pah[t][2 * hj]     = *(const uint32_t*)&x01;
                pah[t][2 * hj + 1] = *(const uint32_t*)&x23;
                pal[t][2 * hj]     = *(const uint32_t*)&y01;
                pal[t][2 * hj + 1] = *(const uint32_t*)&y23;
            }
        }

        // ---- O += P V (3-split; V fragments via ldmatrix.trans) ----
        #pragma unroll
        for (int t = 0; t < 4; ++t) {
            #pragma unroll
            for (int jp = 0; jp < 4; ++jp) {
                const uint32_t va = kbuf + 2 * KVARR
                    + (t * 16 + (lane & 7) + ((lane >> 3) & 1) * 8) * FP
                    + jp * 32 + ((lane >> 4) & 1) * 16;
                uint32_t vh[4], vl[4];
                LDSM4T(vh[0], vh[1], vh[2], vh[3], va);
                LDSM4T(vl[0], vl[1], vl[2], vl[3], va + KVARR);
                mma16816(o[2 * jp],     pah[t], vh);
                mma16816(o[2 * jp],     pah[t], vl);
                mma16816(o[2 * jp],     pal[t], vh);
                mma16816(o[2 * jp + 1], pah[t], vh + 2);
                mma16816(o[2 * jp + 1], pah[t], vl + 2);
                mma16816(o[2 * jp + 1], pal[t], vh + 2);
            }
        }

        __syncthreads();
    }

    // ---- epilogue: normalize, split hi/lo, write ctx ----
    const float i0 = 1.0f / lrow[0];
    const float i1 = 1.0f / lrow[1];
    const int row0 = qt * 64 + wid * 16 + tr;
    const size_t g0 = ((size_t)(bb * SEQ) + row0) * Dm + hh * 64 + tc;
    #pragma unroll
    for (int j = 0; j < 8; ++j) {
        const float a0 = o[j][0] * i0, a1 = o[j][1] * i0;
        const float a2 = o[j][2] * i1, a3 = o[j][3] * i1;
        const __nv_bfloat162 h01 = __floats2bfloat162_rn(a0, a1);
        const __nv_bfloat162 l01 = __floats2bfloat162_rn(
            a0 - __low2float(h01), a1 - __high2float(h01));
        const __nv_bfloat162 h23 = __floats2bfloat162_rn(a2, a3);
        const __nv_bfloat162 l23 = __floats2bfloat162_rn(
            a2 - __low2float(h23), a3 - __high2float(h23));
        *(__nv_bfloat162*)(chi + g0 + j * 8)          = h01;
        *(__nv_bfloat162*)(clo + g0 + j * 8)          = l01;
        *(__nv_bfloat162*)(chi + g0 + 8 * Dm + j * 8) = h23;
        *(__nv_bfloat162*)(clo + g0 + 8 * Dm + j * 8) = l23;
    }
}

// ---------------------------------------------------------------------------
// Launch
// ---------------------------------------------------------------------------
extern "C" void kernel_launch(void* const* d_in, const int* in_sizes, int n_in,
                              void* d_out, int out_size)
{
    const float* hidden    = (const float*)d_in[0];
    const float* ln1_g     = (const float*)d_in[2];
    const float* ln1_b     = (const float*)d_in[3];
    const float* w_attn    = (const float*)d_in[4];
    const float* b_attn    = (const float*)d_in[5];
    const float* w_cproj   = (const float*)d_in[6];
    const float* b_cproj   = (const float*)d_in[7];
    const float* ln2_g     = (const float*)d_in[8];
    const float* ln2_b     = (const float*)d_in[9];
    const float* w_fc      = (const float*)d_in[10];
    const float* b_fc      = (const float*)d_in[11];
    const float* w_fc_proj = (const float*)d_in[12];
    const float* b_fc_proj = (const float*)d_in[13];
    float* out = (float*)d_out;

    float* h;
    __nv_bfloat16 *qvh, *qvl, *xh, *xl, *ch, *cl, *yh, *yl, *ah, *al;
    __nv_bfloat16 *wah, *wal, *wch, *wcl, *wfh, *wfl, *wph, *wpl;
    cudaGetSymbolAddress((void**)&h,   g_h);
    cudaGetSymbolAddress((void**)&qvh, g_qkv_hi);  cudaGetSymbolAddress((void**)&qvl, g_qkv_lo);
    cudaGetSymbolAddress((void**)&xh, g_xln_hi);   cudaGetSymbolAddress((void**)&xl, g_xln_lo);
    cudaGetSymbolAddress((void**)&ch, g_ctx_hi);   cudaGetSymbolAddress((void**)&cl, g_ctx_lo);
    cudaGetSymbolAddress((void**)&yh, g_yln_hi);   cudaGetSymbolAddress((void**)&yl, g_yln_lo);
    cudaGetSymbolAddress((void**)&ah, g_act_hi);   cudaGetSymbolAddress((void**)&al, g_act_lo);
    cudaGetSymbolAddress((void**)&wah, g_wT_attn_hi); cudaGetSymbolAddress((void**)&wal, g_wT_attn_lo);
    cudaGetSymbolAddress((void**)&wch, g_wT_cprj_hi); cudaGetSymbolAddress((void**)&wcl, g_wT_cprj_lo);
    cudaGetSymbolAddress((void**)&wfh, g_wT_fc_hi);   cudaGetSymbolAddress((void**)&wfl, g_wT_fc_lo);
    cudaGetSymbolAddress((void**)&wph, g_wT_fcp_hi);  cudaGetSymbolAddress((void**)&wpl, g_wT_fcp_lo);

    cudaFuncSetAttribute(gemm_mma<2>, cudaFuncAttributeMaxDynamicSharedMemorySize, GSMEM_SIZE);
    cudaFuncSetAttribute(gemm_mma<3>, cudaFuncAttributeMaxDynamicSharedMemorySize, GSMEM_SIZE);
    cudaFuncSetAttribute(gemm_mma<4>, cudaFuncAttributeMaxDynamicSharedMemorySize, GSMEM_SIZE);
    cudaFuncSetAttribute(flash_mma,   cudaFuncAttributeMaxDynamicSharedMemorySize, FSMEM);

    const dim3 tb(32, 8);
    wprep<<<dim3(D3 / 32,     Dm / 32),     tb>>>(w_attn,    wah, wal, Dm,     D3);
    wprep<<<dim3(Dm / 32,     Dm / 32),     tb>>>(w_cproj,   wch, wcl, Dm,     Dm);
    wprep<<<dim3(INNERD / 32, Dm / 32),     tb>>>(w_fc,      wfh, wfl, Dm,     INNERD);
    wprep<<<dim3(Dm / 32,     INNERD / 32), tb>>>(w_fc_proj, wph, wpl, INNERD, Dm);

    // 1. LN1 -> bf16 hi/lo
    layernorm_hilo<<<Mrows, 256>>>(hidden, ln1_g, ln1_b, xh, xl);
    // 2. QKV projection -> bf16 hi/lo (Q pre-scaled)
    gemm_mma<4><<<dim3(D3 / 128, Mrows / 128), 256, GSMEM_SIZE>>>(
        xh, xl, wah, wal, b_attn, nullptr, nullptr, qvh, qvl, Mrows, D3, Dm);
    // 3. Flash attention (mma, 64-q tiles, longest-first) -> ctx hi/lo
    flash_mma<<<dim3(SEQ / 64, BATCH * NHEAD), 128, FSMEM>>>(qvh, qvl, ch, cl);
    // 4. cproj + residual -> h (fp32)
    gemm_mma<2><<<dim3(Dm / 128, Mrows / 128), 256, GSMEM_SIZE>>>(
        ch, cl, wch, wcl, b_cproj, hidden, h, nullptr, nullptr, Mrows, Dm, Dm);
    // 5. LN2 -> yln hi/lo
    layernorm_hilo<<<Mrows, 256>>>(h, ln2_g, ln2_b, yh, yl);
    // 6. fc + GELU -> act hi/lo
    gemm_mma<3><<<dim3(INNERD / 128, Mrows / 128), 256, GSMEM_SIZE>>>(
        yh, yl, wfh, wfl, b_fc, nullptr, nullptr, ah, al, Mrows, INNERD, Dm);
    // 7. fc_proj + residual -> out
    gemm_mma<2><<<dim3(Dm / 128, Mrows / 128), 256, GSMEM_SIZE>>>(
        ah, al, wph, wpl, b_fc_proj, h, out, nullptr, nullptr, Mrows, Dm, INNERD);
}

// round 13
// speedup vs baseline: 3.3443x; 1.0875x over previous
#include <cuda_runtime.h>
#include <cuda_bf16.h>
#include <cstdint>

// ---------------------------------------------------------------------------
// GPT-2 block. B=2, S=4096, D=768, H=12, HD=64, INNER=3072. M = B*S = 8192.
// GEMMs + flash attention all via mma.sync bf16 (3-split hi/lo, fp32 accum).
// GEMM: 2-stage cp.async, 80KB smem, 2 CTAs/SM. Flash: 64-q tiles, 2 CTAs/SM.
// ---------------------------------------------------------------------------

#define Mrows  8192
#define Dm     768
#define D3     2304
#define INNERD 3072
#define NHEAD  12
#define HD     64
#define SEQ    4096
#define BATCH  2

// ------------------------------- scratch -----------------------------------
__device__ float g_h[Mrows * Dm];

__device__ __nv_bfloat16 g_qkv_hi[Mrows * D3];
__device__ __nv_bfloat16 g_qkv_lo[Mrows * D3];
__device__ __nv_bfloat16 g_xln_hi[Mrows * Dm];
__device__ __nv_bfloat16 g_xln_lo[Mrows * Dm];
__device__ __nv_bfloat16 g_ctx_hi[Mrows * Dm];
__device__ __nv_bfloat16 g_ctx_lo[Mrows * Dm];
__device__ __nv_bfloat16 g_yln_hi[Mrows * Dm];
__device__ __nv_bfloat16 g_yln_lo[Mrows * Dm];
__device__ __nv_bfloat16 g_act_hi[Mrows * INNERD];
__device__ __nv_bfloat16 g_act_lo[Mrows * INNERD];

__device__ __nv_bfloat16 g_wT_attn_hi[D3 * Dm];
__device__ __nv_bfloat16 g_wT_attn_lo[D3 * Dm];
__device__ __nv_bfloat16 g_wT_cprj_hi[Dm * Dm];
__device__ __nv_bfloat16 g_wT_cprj_lo[Dm * Dm];
__device__ __nv_bfloat16 g_wT_fc_hi  [INNERD * Dm];
__device__ __nv_bfloat16 g_wT_fc_lo  [INNERD * Dm];
__device__ __nv_bfloat16 g_wT_fcp_hi [Dm * INNERD];
__device__ __nv_bfloat16 g_wT_fcp_lo [Dm * INNERD];

// --------------------------- PTX helpers -----------------------------------
__device__ __forceinline__ uint32_t smem_u32(const void* p) {
    uint32_t a;
    asm("{ .reg .u64 t; cvta.to.shared.u64 t, %1; cvt.u32.u64 %0, t; }"
        : "=r"(a) : "l"(p));
    return a;
}

__device__ __forceinline__ void cpasync16(uint32_t dst, const void* src) {
    asm volatile("cp.async.cg.shared.global [%0], [%1], 16;"
                 :: "r"(dst), "l"(src));
}
__device__ __forceinline__ void cp_commit() {
    asm volatile("cp.async.commit_group;" ::: "memory");
}
__device__ __forceinline__ void cp_wait0() {
    asm volatile("cp.async.wait_group 0;" ::: "memory");
}
__device__ __forceinline__ void cp_wait1() {
    asm volatile("cp.async.wait_group 1;" ::: "memory");
}

#define LDSM4(r0, r1, r2, r3, addr) \
    asm volatile("ldmatrix.sync.aligned.m8n8.x4.shared.b16 {%0,%1,%2,%3}, [%4];" \
                 : "=r"(r0), "=r"(r1), "=r"(r2), "=r"(r3) : "r"(addr))

#define LDSM4T(r0, r1, r2, r3, addr) \
    asm volatile("ldmatrix.sync.aligned.m8n8.x4.trans.shared.b16 {%0,%1,%2,%3}, [%4];" \
                 : "=r"(r0), "=r"(r1), "=r"(r2), "=r"(r3) : "r"(addr))

__device__ __forceinline__ void mma16816(float* d, const uint32_t* a,
                                         const uint32_t* b) {
    asm volatile(
        "mma.sync.aligned.m16n8k16.row.col.f32.bf16.bf16.f32 "
        "{%0,%1,%2,%3}, {%4,%5,%6,%7}, {%8,%9}, {%0,%1,%2,%3};"
        : "+f"(d[0]), "+f"(d[1]), "+f"(d[2]), "+f"(d[3])
        : "r"(a[0]), "r"(a[1]), "r"(a[2]), "r"(a[3]), "r"(b[0]), "r"(b[1]));
}

// ---------------------------------------------------------------------------
// Weight prep: W[K,N] fp32 -> T[N,K] bf16 hi + lo (transpose + split)
// ---------------------------------------------------------------------------
__global__ void wprep(const float* __restrict__ W,
                      __nv_bfloat16* __restrict__ Thi,
                      __nv_bfloat16* __restrict__ Tlo, int K, int N)
{
    __shared__ float t[32][33];
    const int n0 = blockIdx.x * 32, k0 = blockIdx.y * 32;
    const int tx = threadIdx.x, ty = threadIdx.y;
    #pragma unroll
    for (int i = 0; i < 4; ++i)
        t[ty + i * 8][tx] = W[(size_t)(k0 + ty + i * 8) * N + n0 + tx];
    __syncthreads();
    #pragma unroll
    for (int i = 0; i < 4; ++i) {
        const float f = t[tx][ty + i * 8];
        const __nv_bfloat16 hi = __float2bfloat16(f);
        const float lo = f - __bfloat162float(hi);
        const size_t o = (size_t)(n0 + ty + i * 8) * K + k0 + tx;
        Thi[o] = hi;
        Tlo[o] = __float2bfloat16(lo);
    }
}

// ---------------------------------------------------------------------------
// LayerNorm producing bf16 hi/lo split
// ---------------------------------------------------------------------------
__global__ void layernorm_hilo(const float* __restrict__ x,
                               const float* __restrict__ g,
                               const float* __restrict__ b,
                               __nv_bfloat16* __restrict__ yhi,
                               __nv_bfloat16* __restrict__ ylo)
{
    __shared__ float red[16];
    const int row = blockIdx.x;
    const float* xr = x + (size_t)row * Dm;
    const int t = threadIdx.x;

    float v0 = xr[t], v1 = xr[t + 256], v2 = xr[t + 512];
    float s  = v0 + v1 + v2;
    float s2 = v0 * v0 + v1 * v1 + v2 * v2;

    #pragma unroll
    for (int o = 16; o >= 1; o >>= 1) {
        s  += __shfl_xor_sync(0xffffffffu, s,  o);
        s2 += __shfl_xor_sync(0xffffffffu, s2, o);
    }
    const int warp = t >> 5, lane = t & 31;
    if (lane == 0) { red[warp] = s; red[8 + warp] = s2; }
    __syncthreads();
    if (warp == 0) {
        float a  = (lane < 8) ? red[lane] : 0.0f;
        float a2 = (lane < 8) ? red[8 + lane] : 0.0f;
        #pragma unroll
        for (int o = 4; o >= 1; o >>= 1) {
            a  += __shfl_xor_sync(0xffffffffu, a,  o);
            a2 += __shfl_xor_sync(0xffffffffu, a2, o);
        }
        if (lane == 0) { red[0] = a; red[1] = a2; }
    }
    __syncthreads();
    const float mean = red[0] * (1.0f / Dm);
    const float var  = red[1] * (1.0f / Dm) - mean * mean;
    const float rstd = rsqrtf(var + 1e-5f);

    const size_t rb = (size_t)row * Dm;
    #pragma unroll
    for (int i = 0; i < 3; ++i) {
        const int c = t + i * 256;
        const float v = (i == 0) ? v0 : (i == 1) ? v1 : v2;
        const float f = (v - mean) * rstd * g[c] + b[c];
        const __nv_bfloat16 hi = __float2bfloat16(f);
        yhi[rb + c] = hi;
        ylo[rb + c] = __float2bfloat16(f - __bfloat162float(hi));
    }
}

// ---------------------------------------------------------------------------
// mma.sync GEMM: 128x128 tile, 8 warps, BK=32, 2-stage cp.async, 2 CTAs/SM.
// EPI 2: fp32 + bias + residual; EPI 3: bias + GELU -> bf16 hi/lo;
// EPI 4: bias (+0.125 on cols<768) -> bf16 hi/lo (QKV producer).
// ---------------------------------------------------------------------------
__device__ __forceinline__ float gelu_exact(float x) {
    return 0.5f * x * (1.0f + erff(x * 0.70710678118654752f));
}

#define ROWB      80
#define ARRB      (128 * ROWB)
#define BUFB      (4 * ARRB)     // 40960 per stage
#define GSMEM_SIZE (2 * BUFB)    // 81920

template <int EPI>
__global__ __launch_bounds__(256, 2)
void gemm_mma(const __nv_bfloat16* __restrict__ Ahi, const __nv_bfloat16* __restrict__ Alo,
              const __nv_bfloat16* __restrict__ Bhi, const __nv_bfloat16* __restrict__ Blo,
              const float* __restrict__ bias, const float* __restrict__ res,
              float* __restrict__ C,
              __nv_bfloat16* __restrict__ Chi, __nv_bfloat16* __restrict__ Clo,
              int M, int N, int K)
{
    extern __shared__ char smem[];
    const uint32_t sbase = smem_u32(smem);
    const int tid  = threadIdx.x;
    const int wid  = tid >> 5;
    const int lane = tid & 31;
    const int brow = blockIdx.y * 128;
    const int bcol = blockIdx.x * 128;

    const int arr  = tid >> 6;
    const int u    = tid & 63;
    const int rowb = u >> 2;
    const int chk  = u & 3;
    const __nv_bfloat16* gsel =
        (arr == 0) ? Ahi : (arr == 1) ? Alo : (arr == 2) ? Bhi : Blo;
    const int gbase_row = (arr < 2) ? brow : bcol;
    const char* gsrc = (const char*)(gsel + (size_t)(gbase_row + rowb) * K) + chk * 16;
    const uint32_t sdst0 = sbase + arr * ARRB + rowb * ROWB + chk * 16;
    const size_t grow16 = (size_t)16 * K * 2;

    const int NC = K >> 5;

    const int m0 = (wid >> 2) * 64;
    const int n0 = (wid & 3) * 32;
    const int a_r = (lane & 7) + ((lane >> 3) & 1) * 8;
    const int a_k = ((lane >> 4) & 1) * 16;
    const int b_r = (lane & 7) + ((lane >> 4) & 1) * 8;
    const int b_k = ((lane >> 3) & 1) * 16;
    const uint32_t aoff = (uint32_t)((m0 + a_r) * ROWB + a_k);
    const uint32_t boff = (uint32_t)((n0 + b_r) * ROWB + b_k);

    float d[4][4][4];
    #pragma unroll
    for (int mi = 0; mi < 4; ++mi)
        #pragma unroll
        for (int ni = 0; ni < 4; ++ni)
            #pragma unroll
            for (int q = 0; q < 4; ++q) d[mi][ni][q] = 0.0f;

    // prologue: stage chunk 0 into buffer 0
    {
        #pragma unroll
        for (int j = 0; j < 8; ++j)
            cpasync16(sdst0 + j * (16 * ROWB), gsrc + j * grow16);
        cp_commit();
    }

    for (int c = 0; c < NC; ++c) {
        cp_wait0();          // chunk c resident
        __syncthreads();     // all warps done with compute c-1 -> its buffer free

        if (c + 1 < NC) {    // stage chunk c+1 into the freed buffer
            const uint32_t sd = sdst0 + (uint32_t)(((c + 1) & 1) ? BUFB : 0);
            const char* gs = gsrc + (size_t)(c + 1) * 64;
            #pragma unroll
            for (int j = 0; j < 8; ++j)
                cpasync16(sd + j * (16 * ROWB), gs + j * grow16);
            cp_commit();
        }

        const uint32_t bufb = sbase + (uint32_t)((c & 1) ? BUFB : 0);
        #pragma unroll
        for (int ks = 0; ks < 2; ++ks) {
            const uint32_t kb = ks * 32;
            uint32_t ah[4][4], al[4][4], bh[4][2], bl[4][2];
            #pragma unroll
            for (int mi = 0; mi < 4; ++mi) {
                LDSM4(ah[mi][0], ah[mi][1], ah[mi][2], ah[mi][3],
                      bufb + aoff + mi * (16 * ROWB) + kb);
                LDSM4(al[mi][0], al[mi][1], al[mi][2], al[mi][3],
                      bufb + ARRB + aoff + mi * (16 * ROWB) + kb);
            }
            #pragma unroll
            for (int nj = 0; nj < 2; ++nj) {
                LDSM4(bh[nj * 2][0], bh[nj * 2][1], bh[nj * 2 + 1][0], bh[nj * 2 + 1][1],
                      bufb + 2 * ARRB + boff + nj * (16 * ROWB) + kb);
                LDSM4(bl[nj * 2][0], bl[nj * 2][1], bl[nj * 2 + 1][0], bl[nj * 2 + 1][1],
                      bufb + 3 * ARRB + boff + nj * (16 * ROWB) + kb);
            }
            #pragma unroll
            for (int mi = 0; mi < 4; ++mi)
                #pragma unroll
                for (int ni = 0; ni < 4; ++ni) {
                    mma16816(d[mi][ni], ah[mi], bh[ni]);
                    mma16816(d[mi][ni], ah[mi], bl[ni]);
                    mma16816(d[mi][ni], al[mi], bh[ni]);
                }
        }
    }

    const int tr = lane >> 2;
    const int tc = (lane & 3) * 2;
    #pragma unroll
    for (int mi = 0; mi < 4; ++mi) {
        #pragma unroll
        for (int half = 0; half < 2; ++half) {
            const int row = brow + m0 + mi * 16 + tr + half * 8;
            #pragma unroll
            for (int ni = 0; ni < 4; ++ni) {
                const int col = bcol + n0 + ni * 8 + tc;
                const float2 bv = *(const float2*)(bias + col);
                float v0 = d[mi][ni][half * 2 + 0] + bv.x;
                float v1 = d[mi][ni][half * 2 + 1] + bv.y;
                if (EPI == 2) {
                    const float2 rv = *(const float2*)(res + (size_t)row * N + col);
                    v0 += rv.x; v1 += rv.y;
                    *(float2*)(C + (size_t)row * N + col) = make_float2(v0, v1);
                }
                if (EPI == 3) {
                    const float gq0 = gelu_exact(v0);
                    const float gq1 = gelu_exact(v1);
                    const __nv_bfloat162 h2 = __floats2bfloat162_rn(gq0, gq1);
                    const __nv_bfloat162 l2 = __floats2bfloat162_rn(
                        gq0 - __low2float(h2), gq1 - __high2float(h2));
                    *(__nv_bfloat162*)(Chi + (size_t)row * N + col) = h2;
                    *(__nv_bfloat162*)(Clo + (size_t)row * N + col) = l2;
                }
                if (EPI == 4) {
                    const float s4 = (col < 768) ? 0.125f : 1.0f;
                    const float q0 = v0 * s4, q1 = v1 * s4;
                    const __nv_bfloat162 h2 = __floats2bfloat162_rn(q0, q1);
                    const __nv_bfloat162 l2 = __floats2bfloat162_rn(
                        q0 - __low2float(h2), q1 - __high2float(h2));
                    *(__nv_bfloat162*)(Chi + (size_t)row * N + col) = h2;
                    *(__nv_bfloat162*)(Clo + (size_t)row * N + col) = l2;
                }
            }
        }
    }
}

// ---------------------------------------------------------------------------
// Flash attention via mma.sync bf16 3-split.
// 64-q tiles, 128 threads (4 warps x 16 rows), 2 CTAs/SM, longest-first.
// K chunks of 64, double-buffered cp.async K/V.
// ---------------------------------------------------------------------------
#define FP    144                 // smem row pitch bytes (64 bf16 + 16B pad)
#define FQH   0
#define FQL   9216                // 64*144
#define FKV0  18432
#define KVARR 9216                // 64*144
#define KVBUF (4 * KVARR)         // Kh,Kl,Vh,Vl
#define FSMEM (FKV0 + 2 * KVBUF)  // 92160

__global__ __launch_bounds__(128, 2)
void flash_mma(const __nv_bfloat16* __restrict__ qkvh,
               const __nv_bfloat16* __restrict__ qkvl,
               __nv_bfloat16* __restrict__ chi,
               __nv_bfloat16* __restrict__ clo)
{
    extern __shared__ char fs[];
    const uint32_t sb = smem_u32(fs);
    const int tid = threadIdx.x, wid = tid >> 5, lane = tid & 31;
    const int bb = blockIdx.y / NHEAD, hh = blockIdx.y % NHEAD;
    const int qt = (SEQ / 64 - 1) - blockIdx.x;   // longest-first
    const int NC = qt + 1;

    const size_t bbase = (size_t)bb * SEQ * D3;

    // ---- stage Q hi+lo (group 0) ----
    {
        const int qc = tid & 7, qr = tid >> 3;     // qr 0..15
        #pragma unroll
        for (int part = 0; part < 2; ++part) {
            const __nv_bfloat16* src = (part ? qkvl : qkvh) + bbase
                + (size_t)(qt * 64 + qr) * D3 + hh * 64 + qc * 8;
            const uint32_t dst = sb + (part ? FQL : FQH) + qr * FP + qc * 16;
            #pragma unroll
            for (int i = 0; i < 4; ++i)
                cpasync16(dst + i * 16 * FP, src + (size_t)i * 16 * D3);
        }
        cp_commit();
    }

    // ---- K/V staging pointers: 4 arrays x 32 threads ----
    const int arr = tid >> 5;               // 0 Kh 1 Kl 2 Vh 3 Vl
    const int u = tid & 31;
    const int c = u & 7, r = u >> 3;        // r 0..3
    const __nv_bfloat16* kvsrc0 = ((arr & 1) ? qkvl : qkvh) + bbase
        + (size_t)r * D3 + ((arr < 2) ? 768 : 1536) + hh * 64 + c * 8;
    const uint32_t kvdst0 = sb + FKV0 + arr * KVARR + r * FP + c * 16;

    // stage chunk 0 (group 1)
    #pragma unroll
    for (int i = 0; i < 16; ++i)
        cpasync16(kvdst0 + i * 4 * FP, kvsrc0 + (size_t)i * 4 * D3);
    cp_commit();

    // ---- per-warp state ----
    uint32_t qfh[4][4], qfl[4][4];
    float o[8][4];
    float mrow[2] = {-1e30f, -1e30f};
    float lrow[2] = {0.0f, 0.0f};
    #pragma unroll
    for (int j = 0; j < 8; ++j)
        #pragma unroll
        for (int q = 0; q < 4; ++q) o[j][q] = 0.0f;

    const uint32_t qlda = (uint32_t)((wid * 16 + (lane & 7) + 8 * ((lane >> 3) & 1)) * FP
                                     + ((lane >> 4) & 1) * 16);
    const int tr = lane >> 2;
    const int tc = (lane & 3) * 2;

    for (int kt = 0; kt < NC; ++kt) {
        if (kt + 1 < NC) {
            const __nv_bfloat16* s = kvsrc0 + (size_t)(kt + 1) * 64 * D3;
            const uint32_t d0 = kvdst0 + (((kt + 1) & 1) ? KVBUF : 0u);
            #pragma unroll
            for (int i = 0; i < 16; ++i)
                cpasync16(d0 + i * 4 * FP, s + (size_t)i * 4 * D3);
        }
        cp_commit();
        cp_wait1();
        __syncthreads();

        if (kt == 0) {
            #pragma unroll
            for (int s = 0; s < 4; ++s) {
                LDSM4(qfh[s][0], qfh[s][1], qfh[s][2], qfh[s][3],
                      sb + FQH + qlda + s * 32);
                LDSM4(qfl[s][0], qfl[s][1], qfl[s][2], qfl[s][3],
                      sb + FQL + qlda + s * 32);
            }
        }

        const uint32_t kbuf = sb + FKV0 + (uint32_t)((kt & 1) ? KVBUF : 0u);

        // ---- S = Q K^T (3-split) ----
        float sacc[8][4];
        #pragma unroll
        for (int j = 0; j < 8; ++j)
            #pragma unroll
            for (int q = 0; q < 4; ++q) sacc[j][q] = 0.0f;

        #pragma unroll
        for (int j = 0; j < 8; ++j) {
            uint32_t bhf[4][2], blf[4][2];
            const uint32_t ka = kbuf + (j * 8 + (lane & 7)) * FP + ((lane >> 3) & 3) * 16;
            LDSM4(bhf[0][0], bhf[0][1], bhf[1][0], bhf[1][1], ka);
            LDSM4(bhf[2][0], bhf[2][1], bhf[3][0], bhf[3][1], ka + 64);
            LDSM4(blf[0][0], blf[0][1], blf[1][0], blf[1][1], ka + KVARR);
            LDSM4(blf[2][0], blf[2][1], blf[3][0], blf[3][1], ka + KVARR + 64);
            #pragma unroll
            for (int s = 0; s < 4; ++s) {
                mma16816(sacc[j], qfh[s], bhf[s]);
                mma16816(sacc[j], qfh[s], blf[s]);
                mma16816(sacc[j], qfl[s], bhf[s]);
            }
        }

        // ---- causal mask (diagonal chunk only) ----
        if (kt == qt) {
            const int row0 = qt * 64 + wid * 16 + tr;
            const int col0 = kt * 64 + tc;
            #pragma unroll
            for (int j = 0; j < 8; ++j) {
                const int cj = col0 + j * 8;
                if (cj     > row0)     sacc[j][0] = -1e30f;
                if (cj + 1 > row0)     sacc[j][1] = -1e30f;
                if (cj     > row0 + 8) sacc[j][2] = -1e30f;
                if (cj + 1 > row0 + 8) sacc[j][3] = -1e30f;
            }
        }

        // ---- online softmax (rows spread over lane quads) ----
        #pragma unroll
        for (int rr = 0; rr < 2; ++rr) {
            float mc = -1e30f;
            #pragma unroll
            for (int j = 0; j < 8; ++j)
                mc = fmaxf(mc, fmaxf(sacc[j][2 * rr], sacc[j][2 * rr + 1]));
            mc = fmaxf(mc, __shfl_xor_sync(0xffffffffu, mc, 1));
            mc = fmaxf(mc, __shfl_xor_sync(0xffffffffu, mc, 2));
            const float mn = fmaxf(mrow[rr], mc);
            const float alpha = __expf(mrow[rr] - mn);
            float ssum = 0.0f;
            #pragma unroll
            for (int j = 0; j < 8; ++j) {
                const float p0 = __expf(sacc[j][2 * rr]     - mn);
                const float p1 = __expf(sacc[j][2 * rr + 1] - mn);
                sacc[j][2 * rr] = p0; sacc[j][2 * rr + 1] = p1;
                ssum += p0 + p1;
            }
            ssum += __shfl_xor_sync(0xffffffffu, ssum, 1);
            ssum += __shfl_xor_sync(0xffffffffu, ssum, 2);
            lrow[rr] = lrow[rr] * alpha + ssum;
            mrow[rr] = mn;
            #pragma unroll
            for (int j = 0; j < 8; ++j) {
                o[j][2 * rr]     *= alpha;
                o[j][2 * rr + 1] *= alpha;
            }
        }

        // ---- pack P into A-fragments (hi + lo) ----
        uint32_t pah[4][4], pal[4][4];
        #pragma unroll
        for (int t = 0; t < 4; ++t) {
            #pragma unroll
            for (int hj = 0; hj < 2; ++hj) {
                const int j = 2 * t + hj;
                const __nv_bfloat162 x01 = __floats2bfloat162_rn(sacc[j][0], sacc[j][1]);
                const __nv_bfloat162 x23 = __floats2bfloat162_rn(sacc[j][2], sacc[j][3]);
                const __nv_bfloat162 y01 = __floats2bfloat162_rn(
                    sacc[j][0] - __low2float(x01), sacc[j][1] - __high2float(x01));
                const __nv_bfloat162 y23 = __floats2bfloat162_rn(
                    sacc[j][2] - __low2float(x23), sacc[j][3] - __high2float(x23));
                pah[t][2 * hj]     = *(const uint32_t*)&x01;
                pah[t][2 * hj + 1] = *(const uint32_t*)&x23;
                pal[t][2 * hj]     = *(const uint32_t*)&y01;
                pal[t][2 * hj + 1] = *(const uint32_t*)&y23;
            }
        }

        // ---- O += P V (3-split; V fragments via ldmatrix.trans) ----
        #pragma unroll
        for (int t = 0; t < 4; ++t) {
            #pragma unroll
            for (int jp = 0; jp < 4; ++jp) {
                const uint32_t va = kbuf + 2 * KVARR
                    + (t * 16 + (lane & 7) + ((lane >> 3) & 1) * 8) * FP
                    + jp * 32 + ((lane >> 4) & 1) * 16;
                uint32_t vh[4], vl[4];
                LDSM4T(vh[0], vh[1], vh[2], vh[3], va);
                LDSM4T(vl[0], vl[1], vl[2], vl[3], va + KVARR);
                mma16816(o[2 * jp],     pah[t], vh);
                mma16816(o[2 * jp],     pah[t], vl);
                mma16816(o[2 * jp],     pal[t], vh);
                mma16816(o[2 * jp + 1], pah[t], vh + 2);
                mma16816(o[2 * jp + 1], pah[t], vl + 2);
                mma16816(o[2 * jp + 1], pal[t], vh + 2);
            }
        }

        __syncthreads();
    }

    // ---- epilogue: normalize, split hi/lo, write ctx ----
    const float i0 = 1.0f / lrow[0];
    const float i1 = 1.0f / lrow[1];
    const int row0 = qt * 64 + wid * 16 + tr;
    const size_t g0 = ((size_t)(bb * SEQ) + row0) * Dm + hh * 64 + tc;
    #pragma unroll
    for (int j = 0; j < 8; ++j) {
        const float a0 = o[j][0] * i0, a1 = o[j][1] * i0;
        const float a2 = o[j][2] * i1, a3 = o[j][3] * i1;
        const __nv_bfloat162 h01 = __floats2bfloat162_rn(a0, a1);
        const __nv_bfloat162 l01 = __floats2bfloat162_rn(
            a0 - __low2float(h01), a1 - __high2float(h01));
        const __nv_bfloat162 h23 = __floats2bfloat162_rn(a2, a3);
        const __nv_bfloat162 l23 = __floats2bfloat162_rn(
            a2 - __low2float(h23), a3 - __high2float(h23));
        *(__nv_bfloat162*)(chi + g0 + j * 8)          = h01;
        *(__nv_bfloat162*)(clo + g0 + j * 8)          = l01;
        *(__nv_bfloat162*)(chi + g0 + 8 * Dm + j * 8) = h23;
        *(__nv_bfloat162*)(clo + g0 + 8 * Dm + j * 8) = l23;
    }
}

// ---------------------------------------------------------------------------
// Launch
// ---------------------------------------------------------------------------
extern "C" void kernel_launch(void* const* d_in, const int* in_sizes, int n_in,
                              void* d_out, int out_size)
{
    const float* hidden    = (const float*)d_in[0];
    const float* ln1_g     = (const float*)d_in[2];
    const float* ln1_b     = (const float*)d_in[3];
    const float* w_attn    = (const float*)d_in[4];
    const float* b_attn    = (const float*)d_in[5];
    const float* w_cproj   = (const float*)d_in[6];
    const float* b_cproj   = (const float*)d_in[7];
    const float* ln2_g     = (const float*)d_in[8];
    const float* ln2_b     = (const float*)d_in[9];
    const float* w_fc      = (const float*)d_in[10];
    const float* b_fc      = (const float*)d_in[11];
    const float* w_fc_proj = (const float*)d_in[12];
    const float* b_fc_proj = (const float*)d_in[13];
    float* out = (float*)d_out;

    float* h;
    __nv_bfloat16 *qvh, *qvl, *xh, *xl, *ch, *cl, *yh, *yl, *ah, *al;
    __nv_bfloat16 *wah, *wal, *wch, *wcl, *wfh, *wfl, *wph, *wpl;
    cudaGetSymbolAddress((void**)&h,   g_h);
    cudaGetSymbolAddress((void**)&qvh, g_qkv_hi);  cudaGetSymbolAddress((void**)&qvl, g_qkv_lo);
    cudaGetSymbolAddress((void**)&xh, g_xln_hi);   cudaGetSymbolAddress((void**)&xl, g_xln_lo);
    cudaGetSymbolAddress((void**)&ch, g_ctx_hi);   cudaGetSymbolAddress((void**)&cl, g_ctx_lo);
    cudaGetSymbolAddress((void**)&yh, g_yln_hi);   cudaGetSymbolAddress((void**)&yl, g_yln_lo);
    cudaGetSymbolAddress((void**)&ah, g_act_hi);   cudaGetSymbolAddress((void**)&al, g_act_lo);
    cudaGetSymbolAddress((void**)&wah, g_wT_attn_hi); cudaGetSymbolAddress((void**)&wal, g_wT_attn_lo);
    cudaGetSymbolAddress((void**)&wch, g_wT_cprj_hi); cudaGetSymbolAddress((void**)&wcl, g_wT_cprj_lo);
    cudaGetSymbolAddress((void**)&wfh, g_wT_fc_hi);   cudaGetSymbolAddress((void**)&wfl, g_wT_fc_lo);
    cudaGetSymbolAddress((void**)&wph, g_wT_fcp_hi);  cudaGetSymbolAddress((void**)&wpl, g_wT_fcp_lo);

    cudaFuncSetAttribute(gemm_mma<2>, cudaFuncAttributeMaxDynamicSharedMemorySize, GSMEM_SIZE);
    cudaFuncSetAttribute(gemm_mma<3>, cudaFuncAttributeMaxDynamicSharedMemorySize, GSMEM_SIZE);
    cudaFuncSetAttribute(gemm_mma<4>, cudaFuncAttributeMaxDynamicSharedMemorySize, GSMEM_SIZE);
    cudaFuncSetAttribute(flash_mma,   cudaFuncAttributeMaxDynamicSharedMemorySize, FSMEM);

    const dim3 tb(32, 8);
    wprep<<<dim3(D3 / 32,     Dm / 32),     tb>>>(w_attn,    wah, wal, Dm,     D3);
    wprep<<<dim3(Dm / 32,     Dm / 32),     tb>>>(w_cproj,   wch, wcl, Dm,     Dm);
    wprep<<<dim3(INNERD / 32, Dm / 32),     tb>>>(w_fc,      wfh, wfl, Dm,     INNERD);
    wprep<<<dim3(Dm / 32,     INNERD / 32), tb>>>(w_fc_proj, wph, wpl, INNERD, Dm);

    // 1. LN1 -> bf16 hi/lo
    layernorm_hilo<<<Mrows, 256>>>(hidden, ln1_g, ln1_b, xh, xl);
    // 2. QKV projection -> bf16 hi/lo (Q pre-scaled)
    gemm_mma<4><<<dim3(D3 / 128, Mrows / 128), 256, GSMEM_SIZE>>>(
        xh, xl, wah, wal, b_attn, nullptr, nullptr, qvh, qvl, Mrows, D3, Dm);
    // 3. Flash attention (mma, 64-q tiles, longest-first) -> ctx hi/lo
    flash_mma<<<dim3(SEQ / 64, BATCH * NHEAD), 128, FSMEM>>>(qvh, qvl, ch, cl);
    // 4. cproj + residual -> h (fp32)
    gemm_mma<2><<<dim3(Dm / 128, Mrows / 128), 256, GSMEM_SIZE>>>(
        ch, cl, wch, wcl, b_cproj, hidden, h, nullptr, nullptr, Mrows, Dm, Dm);
    // 5. LN2 -> yln hi/lo
    layernorm_hilo<<<Mrows, 256>>>(h, ln2_g, ln2_b, yh, yl);
    // 6. fc + GELU -> act hi/lo
    gemm_mma<3><<<dim3(INNERD / 128, Mrows / 128), 256, GSMEM_SIZE>>>(
        yh, yl, wfh, wfl, b_fc, nullptr, nullptr, ah, al, Mrows, INNERD, Dm);
    // 7. fc_proj + residual -> out
    gemm_mma<2><<<dim3(Dm / 128, Mrows / 128), 256, GSMEM_SIZE>>>(
        ah, al, wph, wpl, b_fc_proj, h, out, nullptr, nullptr, Mrows, Dm, INNERD);
}

// round 15
// speedup vs baseline: 3.3477x; 1.0010x over previous
#include <cuda_runtime.h>
#include <cuda_bf16.h>
#include <cstdint>

// ---------------------------------------------------------------------------
// GPT-2 block. B=2, S=4096, D=768, H=12, HD=64, INNER=3072. M = B*S = 8192.
// GEMMs + flash attention all via mma.sync bf16 (3-split hi/lo, fp32 accum).
// GEMM: 2-stage cp.async, 80KB smem, 2 CTAs/SM, low-liveness fragment schedule.
// ---------------------------------------------------------------------------

#define Mrows  8192
#define Dm     768
#define D3     2304
#define INNERD 3072
#define NHEAD  12
#define HD     64
#define SEQ    4096
#define BATCH  2

// ------------------------------- scratch -----------------------------------
__device__ float g_h[Mrows * Dm];

__device__ __nv_bfloat16 g_qkv_hi[Mrows * D3];
__device__ __nv_bfloat16 g_qkv_lo[Mrows * D3];
__device__ __nv_bfloat16 g_xln_hi[Mrows * Dm];
__device__ __nv_bfloat16 g_xln_lo[Mrows * Dm];
__device__ __nv_bfloat16 g_ctx_hi[Mrows * Dm];
__device__ __nv_bfloat16 g_ctx_lo[Mrows * Dm];
__device__ __nv_bfloat16 g_yln_hi[Mrows * Dm];
__device__ __nv_bfloat16 g_yln_lo[Mrows * Dm];
__device__ __nv_bfloat16 g_act_hi[Mrows * INNERD];
__device__ __nv_bfloat16 g_act_lo[Mrows * INNERD];

__device__ __nv_bfloat16 g_wT_attn_hi[D3 * Dm];
__device__ __nv_bfloat16 g_wT_attn_lo[D3 * Dm];
__device__ __nv_bfloat16 g_wT_cprj_hi[Dm * Dm];
__device__ __nv_bfloat16 g_wT_cprj_lo[Dm * Dm];
__device__ __nv_bfloat16 g_wT_fc_hi  [INNERD * Dm];
__device__ __nv_bfloat16 g_wT_fc_lo  [INNERD * Dm];
__device__ __nv_bfloat16 g_wT_fcp_hi [Dm * INNERD];
__device__ __nv_bfloat16 g_wT_fcp_lo [Dm * INNERD];

// --------------------------- PTX helpers -----------------------------------
__device__ __forceinline__ uint32_t smem_u32(const void* p) {
    uint32_t a;
    asm("{ .reg .u64 t; cvta.to.shared.u64 t, %1; cvt.u32.u64 %0, t; }"
        : "=r"(a) : "l"(p));
    return a;
}

__device__ __forceinline__ void cpasync16(uint32_t dst, const void* src) {
    asm volatile("cp.async.cg.shared.global [%0], [%1], 16;"
                 :: "r"(dst), "l"(src));
}
__device__ __forceinline__ void cp_commit() {
    asm volatile("cp.async.commit_group;" ::: "memory");
}
__device__ __forceinline__ void cp_wait0() {
    asm volatile("cp.async.wait_group 0;" ::: "memory");
}
__device__ __forceinline__ void cp_wait1() {
    asm volatile("cp.async.wait_group 1;" ::: "memory");
}

#define LDSM4(r0, r1, r2, r3, addr) \
    asm volatile("ldmatrix.sync.aligned.m8n8.x4.shared.b16 {%0,%1,%2,%3}, [%4];" \
                 : "=r"(r0), "=r"(r1), "=r"(r2), "=r"(r3) : "r"(addr))

#define LDSM4T(r0, r1, r2, r3, addr) \
    asm volatile("ldmatrix.sync.aligned.m8n8.x4.trans.shared.b16 {%0,%1,%2,%3}, [%4];" \
                 : "=r"(r0), "=r"(r1), "=r"(r2), "=r"(r3) : "r"(addr))

__device__ __forceinline__ void mma16816(float* d, const uint32_t* a,
                                         const uint32_t* b) {
    asm volatile(
        "mma.sync.aligned.m16n8k16.row.col.f32.bf16.bf16.f32 "
        "{%0,%1,%2,%3}, {%4,%5,%6,%7}, {%8,%9}, {%0,%1,%2,%3};"
        : "+f"(d[0]), "+f"(d[1]), "+f"(d[2]), "+f"(d[3])
        : "r"(a[0]), "r"(a[1]), "r"(a[2]), "r"(a[3]), "r"(b[0]), "r"(b[1]));
}

// ---------------------------------------------------------------------------
// Weight prep: W[K,N] fp32 -> T[N,K] bf16 hi + lo (transpose + split)
// ---------------------------------------------------------------------------
__global__ void wprep(const float* __restrict__ W,
                      __nv_bfloat16* __restrict__ Thi,
                      __nv_bfloat16* __restrict__ Tlo, int K, int N)
{
    __shared__ float t[32][33];
    const int n0 = blockIdx.x * 32, k0 = blockIdx.y * 32;
    const int tx = threadIdx.x, ty = threadIdx.y;
    #pragma unroll
    for (int i = 0; i < 4; ++i)
        t[ty + i * 8][tx] = W[(size_t)(k0 + ty + i * 8) * N + n0 + tx];
    __syncthreads();
    #pragma unroll
    for (int i = 0; i < 4; ++i) {
        const float f = t[tx][ty + i * 8];
        const __nv_bfloat16 hi = __float2bfloat16(f);
        const float lo = f - __bfloat162float(hi);
        const size_t o = (size_t)(n0 + ty + i * 8) * K + k0 + tx;
        Thi[o] = hi;
        Tlo[o] = __float2bfloat16(lo);
    }
}

// ---------------------------------------------------------------------------
// LayerNorm producing bf16 hi/lo split
// ---------------------------------------------------------------------------
__global__ void layernorm_hilo(const float* __restrict__ x,
                               const float* __restrict__ g,
                               const float* __restrict__ b,
                               __nv_bfloat16* __restrict__ yhi,
                               __nv_bfloat16* __restrict__ ylo)
{
    __shared__ float red[16];
    const int row = blockIdx.x;
    const float* xr = x + (size_t)row * Dm;
    const int t = threadIdx.x;

    float v0 = xr[t], v1 = xr[t + 256], v2 = xr[t + 512];
    float s  = v0 + v1 + v2;
    float s2 = v0 * v0 + v1 * v1 + v2 * v2;

    #pragma unroll
    for (int o = 16; o >= 1; o >>= 1) {
        s  += __shfl_xor_sync(0xffffffffu, s,  o);
        s2 += __shfl_xor_sync(0xffffffffu, s2, o);
    }
    const int warp = t >> 5, lane = t & 31;
    if (lane == 0) { red[warp] = s; red[8 + warp] = s2; }
    __syncthreads();
    if (warp == 0) {
        float a  = (lane < 8) ? red[lane] : 0.0f;
        float a2 = (lane < 8) ? red[8 + lane] : 0.0f;
        #pragma unroll
        for (int o = 4; o >= 1; o >>= 1) {
            a  += __shfl_xor_sync(0xffffffffu, a,  o);
            a2 += __shfl_xor_sync(0xffffffffu, a2, o);
        }
        if (lane == 0) { red[0] = a; red[1] = a2; }
    }
    __syncthreads();
    const float mean = red[0] * (1.0f / Dm);
    const float var  = red[1] * (1.0f / Dm) - mean * mean;
    const float rstd = rsqrtf(var + 1e-5f);

    const size_t rb = (size_t)row * Dm;
    #pragma unroll
    for (int i = 0; i < 3; ++i) {
        const int c = t + i * 256;
        const float v = (i == 0) ? v0 : (i == 1) ? v1 : v2;
        const float f = (v - mean) * rstd * g[c] + b[c];
        const __nv_bfloat16 hi = __float2bfloat16(f);
        yhi[rb + c] = hi;
        ylo[rb + c] = __float2bfloat16(f - __bfloat162float(hi));
    }
}

// ---------------------------------------------------------------------------
// mma.sync GEMM: 128x128 tile, 8 warps, BK=32, 2-stage cp.async, 2 CTAs/SM.
// Low-liveness schedule: A-hi and A-lo fragments share registers.
// EPI 2: fp32 + bias + residual; EPI 3: bias + GELU -> bf16 hi/lo;
// EPI 4: bias (+0.125 on cols<768) -> bf16 hi/lo (QKV producer).
// ---------------------------------------------------------------------------
__device__ __forceinline__ float gelu_exact(float x) {
    return 0.5f * x * (1.0f + erff(x * 0.70710678118654752f));
}

#define ROWB      80
#define ARRB      (128 * ROWB)
#define BUFB      (4 * ARRB)     // 40960 per stage
#define GSMEM_SIZE (2 * BUFB)    // 81920

template <int EPI>
__global__ __launch_bounds__(256, 2)
void gemm_mma(const __nv_bfloat16* __restrict__ Ahi, const __nv_bfloat16* __restrict__ Alo,
              const __nv_bfloat16* __restrict__ Bhi, const __nv_bfloat16* __restrict__ Blo,
              const float* __restrict__ bias, const float* __restrict__ res,
              float* __restrict__ C,
              __nv_bfloat16* __restrict__ Chi, __nv_bfloat16* __restrict__ Clo,
              int M, int N, int K)
{
    extern __shared__ char smem[];
    const uint32_t sbase = smem_u32(smem);
    const int tid  = threadIdx.x;
    const int wid  = tid >> 5;
    const int lane = tid & 31;
    const int brow = blockIdx.y * 128;
    const int bcol = blockIdx.x * 128;

    const int arr  = tid >> 6;
    const int u    = tid & 63;
    const int rowb = u >> 2;
    const int chk  = u & 3;
    const __nv_bfloat16* gsel =
        (arr == 0) ? Ahi : (arr == 1) ? Alo : (arr == 2) ? Bhi : Blo;
    const int gbase_row = (arr < 2) ? brow : bcol;
    const char* gsrc = (const char*)(gsel + (size_t)(gbase_row + rowb) * K) + chk * 16;
    const uint32_t sdst0 = sbase + arr * ARRB + rowb * ROWB + chk * 16;
    const size_t grow16 = (size_t)16 * K * 2;

    const int NC = K >> 5;

    const int m0 = (wid >> 2) * 64;
    const int n0 = (wid & 3) * 32;
    const int a_r = (lane & 7) + ((lane >> 3) & 1) * 8;
    const int a_k = ((lane >> 4) & 1) * 16;
    const int b_r = (lane & 7) + ((lane >> 4) & 1) * 8;
    const int b_k = ((lane >> 3) & 1) * 16;
    const uint32_t aoff = (uint32_t)((m0 + a_r) * ROWB + a_k);
    const uint32_t boff = (uint32_t)((n0 + b_r) * ROWB + b_k);

    float d[4][4][4];
    #pragma unroll
    for (int mi = 0; mi < 4; ++mi)
        #pragma unroll
        for (int ni = 0; ni < 4; ++ni)
            #pragma unroll
            for (int q = 0; q < 4; ++q) d[mi][ni][q] = 0.0f;

    // prologue: stage chunk 0 into buffer 0
    {
        #pragma unroll
        for (int j = 0; j < 8; ++j)
            cpasync16(sdst0 + j * (16 * ROWB), gsrc + j * grow16);
        cp_commit();
    }

    for (int c = 0; c < NC; ++c) {
        cp_wait0();          // chunk c resident
        __syncthreads();     // all warps done with compute c-1 -> its buffer free

        if (c + 1 < NC) {    // stage chunk c+1 into the freed buffer
            const uint32_t sd = sdst0 + (uint32_t)(((c + 1) & 1) ? BUFB : 0);
            const char* gs = gsrc + (size_t)(c + 1) * 64;
            #pragma unroll
            for (int j = 0; j < 8; ++j)
                cpasync16(sd + j * (16 * ROWB), gs + j * grow16);
            cp_commit();
        }

        const uint32_t bufb = sbase + (uint32_t)((c & 1) ? BUFB : 0);
        #pragma unroll
        for (int ks = 0; ks < 2; ++ks) {
            const uint32_t kb = ks * 32;
            uint32_t af[4][4], bh[4][2], bl[4][2];

            // ---- phase 1: A-hi fragments + both B splits ----
            #pragma unroll
            for (int mi = 0; mi < 4; ++mi)
                LDSM4(af[mi][0], af[mi][1], af[mi][2], af[mi][3],
                      bufb + aoff + mi * (16 * ROWB) + kb);
            #pragma unroll
            for (int nj = 0; nj < 2; ++nj) {
                LDSM4(bh[nj * 2][0], bh[nj * 2][1], bh[nj * 2 + 1][0], bh[nj * 2 + 1][1],
                      bufb + 2 * ARRB + boff + nj * (16 * ROWB) + kb);
                LDSM4(bl[nj * 2][0], bl[nj * 2][1], bl[nj * 2 + 1][0], bl[nj * 2 + 1][1],
                      bufb + 3 * ARRB + boff + nj * (16 * ROWB) + kb);
            }
            #pragma unroll
            for (int mi = 0; mi < 4; ++mi)
                #pragma unroll
                for (int ni = 0; ni < 4; ++ni) {
                    mma16816(d[mi][ni], af[mi], bh[ni]);
                    mma16816(d[mi][ni], af[mi], bl[ni]);
                }

            // ---- phase 2: A-lo fragments reuse af registers ----
            #pragma unroll
            for (int mi = 0; mi < 4; ++mi)
                LDSM4(af[mi][0], af[mi][1], af[mi][2], af[mi][3],
                      bufb + ARRB + aoff + mi * (16 * ROWB) + kb);
            #pragma unroll
            for (int mi = 0; mi < 4; ++mi)
                #pragma unroll
                for (int ni = 0; ni < 4; ++ni)
                    mma16816(d[mi][ni], af[mi], bh[ni]);
        }
    }

    const int tr = lane >> 2;
    const int tc = (lane & 3) * 2;
    #pragma unroll
    for (int mi = 0; mi < 4; ++mi) {
        #pragma unroll
        for (int half = 0; half < 2; ++half) {
            const int row = brow + m0 + mi * 16 + tr + half * 8;
            #pragma unroll
            for (int ni = 0; ni < 4; ++ni) {
                const int col = bcol + n0 + ni * 8 + tc;
                const float2 bv = *(const float2*)(bias + col);
                float v0 = d[mi][ni][half * 2 + 0] + bv.x;
                float v1 = d[mi][ni][half * 2 + 1] + bv.y;
                if (EPI == 2) {
                    const float2 rv = *(const float2*)(res + (size_t)row * N + col);
                    v0 += rv.x; v1 += rv.y;
                    *(float2*)(C + (size_t)row * N + col) = make_float2(v0, v1);
                }
                if (EPI == 3) {
                    const float gq0 = gelu_exact(v0);
                    const float gq1 = gelu_exact(v1);
                    const __nv_bfloat162 h2 = __floats2bfloat162_rn(gq0, gq1);
                    const __nv_bfloat162 l2 = __floats2bfloat162_rn(
                        gq0 - __low2float(h2), gq1 - __high2float(h2));
                    *(__nv_bfloat162*)(Chi + (size_t)row * N + col) = h2;
                    *(__nv_bfloat162*)(Clo + (size_t)row * N + col) = l2;
                }
                if (EPI == 4) {
                    const float s4 = (col < 768) ? 0.125f : 1.0f;
                    const float q0 = v0 * s4, q1 = v1 * s4;
                    const __nv_bfloat162 h2 = __floats2bfloat162_rn(q0, q1);
                    const __nv_bfloat162 l2 = __floats2bfloat162_rn(
                        q0 - __low2float(h2), q1 - __high2float(h2));
                    *(__nv_bfloat162*)(Chi + (size_t)row * N + col) = h2;
                    *(__nv_bfloat162*)(Clo + (size_t)row * N + col) = l2;
                }
            }
        }
    }
}

// ---------------------------------------------------------------------------
// Flash attention via mma.sync bf16 3-split.
// 64-q tiles, 128 threads (4 warps x 16 rows), 2 CTAs/SM, longest-first.
// K chunks of 64, double-buffered cp.async K/V.
// ---------------------------------------------------------------------------
#define FP    144                 // smem row pitch bytes (64 bf16 + 16B pad)
#define FQH   0
#define FQL   9216                // 64*144
#define FKV0  18432
#define KVARR 9216                // 64*144
#define KVBUF (4 * KVARR)         // Kh,Kl,Vh,Vl
#define FSMEM (FKV0 + 2 * KVBUF)  // 92160

__global__ __launch_bounds__(128, 2)
void flash_mma(const __nv_bfloat16* __restrict__ qkvh,
               const __nv_bfloat16* __restrict__ qkvl,
               __nv_bfloat16* __restrict__ chi,
               __nv_bfloat16* __restrict__ clo)
{
    extern __shared__ char fs[];
    const uint32_t sb = smem_u32(fs);
    const int tid = threadIdx.x, wid = tid >> 5, lane = tid & 31;
    const int bb = blockIdx.y / NHEAD, hh = blockIdx.y % NHEAD;
    const int qt = (SEQ / 64 - 1) - blockIdx.x;   // longest-first
    const int NC = qt + 1;

    const size_t bbase = (size_t)bb * SEQ * D3;

    // ---- stage Q hi+lo (group 0) ----
    {
        const int qc = tid & 7, qr = tid >> 3;     // qr 0..15
        #pragma unroll
        for (int part = 0; part < 2; ++part) {
            const __nv_bfloat16* src = (part ? qkvl : qkvh) + bbase
                + (size_t)(qt * 64 + qr) * D3 + hh * 64 + qc * 8;
            const uint32_t dst = sb + (part ? FQL : FQH) + qr * FP + qc * 16;
            #pragma unroll
            for (int i = 0; i < 4; ++i)
                cpasync16(dst + i * 16 * FP, src + (size_t)i * 16 * D3);
        }
        cp_commit();
    }

    // ---- K/V staging pointers: 4 arrays x 32 threads ----
    const int arr = tid >> 5;               // 0 Kh 1 Kl 2 Vh 3 Vl
    const int u = tid & 31;
    const int c = u & 7, r = u >> 3;        // r 0..3
    const __nv_bfloat16* kvsrc0 = ((arr & 1) ? qkvl : qkvh) + bbase
        + (size_t)r * D3 + ((arr < 2) ? 768 : 1536) + hh * 64 + c * 8;
    const uint32_t kvdst0 = sb + FKV0 + arr * KVARR + r * FP + c * 16;

    // stage chunk 0 (group 1)
    #pragma unroll
    for (int i = 0; i < 16; ++i)
        cpasync16(kvdst0 + i * 4 * FP, kvsrc0 + (size_t)i * 4 * D3);
    cp_commit();

    // ---- per-warp state ----
    uint32_t qfh[4][4], qfl[4][4];
    float o[8][4];
    float mrow[2] = {-1e30f, -1e30f};
    float lrow[2] = {0.0f, 0.0f};
    #pragma unroll
    for (int j = 0; j < 8; ++j)
        #pragma unroll
        for (int q = 0; q < 4; ++q) o[j][q] = 0.0f;

    const uint32_t qlda = (uint32_t)((wid * 16 + (lane & 7) + 8 * ((lane >> 3) & 1)) * FP
                                     + ((lane >> 4) & 1) * 16);
    const int tr = lane >> 2;
    const int tc = (lane & 3) * 2;

    for (int kt = 0; kt < NC; ++kt) {
        if (kt + 1 < NC) {
            const __nv_bfloat16* s = kvsrc0 + (size_t)(kt + 1) * 64 * D3;
            const uint32_t d0 = kvdst0 + (((kt + 1) & 1) ? KVBUF : 0u);
            #pragma unroll
            for (int i = 0; i < 16; ++i)
                cpasync16(d0 + i * 4 * FP, s + (size_t)i * 4 * D3);
        }
        cp_commit();
        cp_wait1();
        __syncthreads();

        if (kt == 0) {
            #pragma unroll
            for (int s = 0; s < 4; ++s) {
                LDSM4(qfh[s][0], qfh[s][1], qfh[s][2], qfh[s][3],
                      sb + FQH + qlda + s * 32);
                LDSM4(qfl[s][0], qfl[s][1], qfl[s][2], qfl[s][3],
                      sb + FQL + qlda + s * 32);
            }
        }

        const uint32_t kbuf = sb + FKV0 + (uint32_t)((kt & 1) ? KVBUF : 0u);

        // ---- S = Q K^T (3-split) ----
        float sacc[8][4];
        #pragma unroll
        for (int j = 0; j < 8; ++j)
            #pragma unroll
            for (int q = 0; q < 4; ++q) sacc[j][q] = 0.0f;

        #pragma unroll
        for (int j = 0; j < 8; ++j) {
            uint32_t bhf[4][2], blf[4][2];
            const uint32_t ka = kbuf + (j * 8 + (lane & 7)) * FP + ((lane >> 3) & 3) * 16;
            LDSM4(bhf[0][0], bhf[0][1], bhf[1][0], bhf[1][1], ka);
            LDSM4(bhf[2][0], bhf[2][1], bhf[3][0], bhf[3][1], ka + 64);
            LDSM4(blf[0][0], blf[0][1], blf[1][0], blf[1][1], ka + KVARR);
            LDSM4(blf[2][0], blf[2][1], blf[3][0], blf[3][1], ka + KVARR + 64);
            #pragma unroll
            for (int s = 0; s < 4; ++s) {
                mma16816(sacc[j], qfh[s], bhf[s]);
                mma16816(sacc[j], qfh[s], blf[s]);
                mma16816(sacc[j], qfl[s], bhf[s]);
            }
        }

        // ---- causal mask (diagonal chunk only) ----
        if (kt == qt) {
            const int row0 = qt * 64 + wid * 16 + tr;
            const int col0 = kt * 64 + tc;
            #pragma unroll
            for (int j = 0; j < 8; ++j) {
                const int cj = col0 + j * 8;
                if (cj     > row0)     sacc[j][0] = -1e30f;
                if (cj + 1 > row0)     sacc[j][1] = -1e30f;
                if (cj     > row0 + 8) sacc[j][2] = -1e30f;
                if (cj + 1 > row0 + 8) sacc[j][3] = -1e30f;
            }
        }

        // ---- online softmax (rows spread over lane quads) ----
        #pragma unroll
        for (int rr = 0; rr < 2; ++rr) {
            float mc = -1e30f;
            #pragma unroll
            for (int j = 0; j < 8; ++j)
                mc = fmaxf(mc, fmaxf(sacc[j][2 * rr], sacc[j][2 * rr + 1]));
            mc = fmaxf(mc, __shfl_xor_sync(0xffffffffu, mc, 1));
            mc = fmaxf(mc, __shfl_xor_sync(0xffffffffu, mc, 2));
            const float mn = fmaxf(mrow[rr], mc);
            const float alpha = __expf(mrow[rr] - mn);
            float ssum = 0.0f;
            #pragma unroll
            for (int j = 0; j < 8; ++j) {
                const float p0 = __expf(sacc[j][2 * rr]     - mn);
                const float p1 = __expf(sacc[j][2 * rr + 1] - mn);
                sacc[j][2 * rr] = p0; sacc[j][2 * rr + 1] = p1;
                ssum += p0 + p1;
            }
            ssum += __shfl_xor_sync(0xffffffffu, ssum, 1);
            ssum += __shfl_xor_sync(0xffffffffu, ssum, 2);
            lrow[rr] = lrow[rr] * alpha + ssum;
            mrow[rr] = mn;
            #pragma unroll
            for (int j = 0; j < 8; ++j) {
                o[j][2 * rr]     *= alpha;
                o[j][2 * rr + 1] *= alpha;
            }
        }

        // ---- pack P into A-fragments (hi + lo) ----
        uint32_t pah[4][4], pal[4][4];
        #pragma unroll
        for (int t = 0; t < 4; ++t) {
            #pragma unroll
            for (int hj = 0; hj < 2; ++hj) {
                const int j = 2 * t + hj;
                const __nv_bfloat162 x01 = __floats2bfloat162_rn(sacc[j][0], sacc[j][1]);
                const __nv_bfloat162 x23 = __floats2bfloat162_rn(sacc[j][2], sacc[j][3]);
                const __nv_bfloat162 y01 = __floats2bfloat162_rn(
                    sacc[j][0] - __low2float(x01), sacc[j][1] - __high2float(x01));
                const __nv_bfloat162 y23 = __floats2bfloat162_rn(
                    sacc[j][2] - __low2float(x23), sacc[j][3] - __high2float(x23));
                pah[t][2 * hj]     = *(const uint32_t*)&x01;
                pah[t][2 * hj + 1] = *(const uint32_t*)&x23;
                pal[t][2 * hj]     = *(const uint32_t*)&y01;
                pal[t][2 * hj + 1] = *(const uint32_t*)&y23;
            }
        }

        // ---- O += P V (3-split; V fragments via ldmatrix.trans) ----
        #pragma unroll
        for (int t = 0; t < 4; ++t) {
            #pragma unroll
            for (int jp = 0; jp < 4; ++jp) {
                const uint32_t va = kbuf + 2 * KVARR
                    + (t * 16 + (lane & 7) + ((lane >> 3) & 1) * 8) * FP
                    + jp * 32 + ((lane >> 4) & 1) * 16;
                uint32_t vh[4], vl[4];
                LDSM4T(vh[0], vh[1], vh[2], vh[3], va);
                LDSM4T(vl[0], vl[1], vl[2], vl[3], va + KVARR);
                mma16816(o[2 * jp],     pah[t], vh);
                mma16816(o[2 * jp],     pah[t], vl);
                mma16816(o[2 * jp],     pal[t], vh);
                mma16816(o[2 * jp + 1], pah[t], vh + 2);
                mma16816(o[2 * jp + 1], pah[t], vl + 2);
                mma16816(o[2 * jp + 1], pal[t], vh + 2);
            }
        }

        __syncthreads();
    }

    // ---- epilogue: normalize, split hi/lo, write ctx ----
    const float i0 = 1.0f / lrow[0];
    const float i1 = 1.0f / lrow[1];
    const int row0 = qt * 64 + wid * 16 + tr;
    const size_t g0 = ((size_t)(bb * SEQ) + row0) * Dm + hh * 64 + tc;
    #pragma unroll
    for (int j = 0; j < 8; ++j) {
        const float a0 = o[j][0] * i0, a1 = o[j][1] * i0;
        const float a2 = o[j][2] * i1, a3 = o[j][3] * i1;
        const __nv_bfloat162 h01 = __floats2bfloat162_rn(a0, a1);
        const __nv_bfloat162 l01 = __floats2bfloat162_rn(
            a0 - __low2float(h01), a1 - __high2float(h01));
        const __nv_bfloat162 h23 = __floats2bfloat162_rn(a2, a3);
        const __nv_bfloat162 l23 = __floats2bfloat162_rn(
            a2 - __low2float(h23), a3 - __high2float(h23));
        *(__nv_bfloat162*)(chi + g0 + j * 8)          = h01;
        *(__nv_bfloat162*)(clo + g0 + j * 8)          = l01;
        *(__nv_bfloat162*)(chi + g0 + 8 * Dm + j * 8) = h23;
        *(__nv_bfloat162*)(clo + g0 + 8 * Dm + j * 8) = l23;
    }
}

// ---------------------------------------------------------------------------
// Launch
// ---------------------------------------------------------------------------
extern "C" void kernel_launch(void* const* d_in, const int* in_sizes, int n_in,
                              void* d_out, int out_size)
{
    const float* hidden    = (const float*)d_in[0];
    const float* ln1_g     = (const float*)d_in[2];
    const float* ln1_b     = (const float*)d_in[3];
    const float* w_attn    = (const float*)d_in[4];
    const float* b_attn    = (const float*)d_in[5];
    const float* w_cproj   = (const float*)d_in[6];
    const float* b_cproj   = (const float*)d_in[7];
    const float* ln2_g     = (const float*)d_in[8];
    const float* ln2_b     = (const float*)d_in[9];
    const float* w_fc      = (const float*)d_in[10];
    const float* b_fc      = (const float*)d_in[11];
    const float* w_fc_proj = (const float*)d_in[12];
    const float* b_fc_proj = (const float*)d_in[13];
    float* out = (float*)d_out;

    float* h;
    __nv_bfloat16 *qvh, *qvl, *xh, *xl, *ch, *cl, *yh, *yl, *ah, *al;
    __nv_bfloat16 *wah, *wal, *wch, *wcl, *wfh, *wfl, *wph, *wpl;
    cudaGetSymbolAddress((void**)&h,   g_h);
    cudaGetSymbolAddress((void**)&qvh, g_qkv_hi);  cudaGetSymbolAddress((void**)&qvl, g_qkv_lo);
    cudaGetSymbolAddress((void**)&xh, g_xln_hi);   cudaGetSymbolAddress((void**)&xl, g_xln_lo);
    cudaGetSymbolAddress((void**)&ch, g_ctx_hi);   cudaGetSymbolAddress((void**)&cl, g_ctx_lo);
    cudaGetSymbolAddress((void**)&yh, g_yln_hi);   cudaGetSymbolAddress((void**)&yl, g_yln_lo);
    cudaGetSymbolAddress((void**)&ah, g_act_hi);   cudaGetSymbolAddress((void**)&al, g_act_lo);
    cudaGetSymbolAddress((void**)&wah, g_wT_attn_hi); cudaGetSymbolAddress((void**)&wal, g_wT_attn_lo);
    cudaGetSymbolAddress((void**)&wch, g_wT_cprj_hi); cudaGetSymbolAddress((void**)&wcl, g_wT_cprj_lo);
    cudaGetSymbolAddress((void**)&wfh, g_wT_fc_hi);   cudaGetSymbolAddress((void**)&wfl, g_wT_fc_lo);
    cudaGetSymbolAddress((void**)&wph, g_wT_fcp_hi);  cudaGetSymbolAddress((void**)&wpl, g_wT_fcp_lo);

    cudaFuncSetAttribute(gemm_mma<2>, cudaFuncAttributeMaxDynamicSharedMemorySize, GSMEM_SIZE);
    cudaFuncSetAttribute(gemm_mma<3>, cudaFuncAttributeMaxDynamicSharedMemorySize, GSMEM_SIZE);
    cudaFuncSetAttribute(gemm_mma<4>, cudaFuncAttributeMaxDynamicSharedMemorySize, GSMEM_SIZE);
    cudaFuncSetAttribute(flash_mma,   cudaFuncAttributeMaxDynamicSharedMemorySize, FSMEM);

    const dim3 tb(32, 8);
    wprep<<<dim3(D3 / 32,     Dm / 32),     tb>>>(w_attn,    wah, wal, Dm,     D3);
    wprep<<<dim3(Dm / 32,     Dm / 32),     tb>>>(w_cproj,   wch, wcl, Dm,     Dm);
    wprep<<<dim3(INNERD / 32, Dm / 32),     tb>>>(w_fc,      wfh, wfl, Dm,     INNERD);
    wprep<<<dim3(Dm / 32,     INNERD / 32), tb>>>(w_fc_proj, wph, wpl, INNERD, Dm);

    // 1. LN1 -> bf16 hi/lo
    layernorm_hilo<<<Mrows, 256>>>(hidden, ln1_g, ln1_b, xh, xl);
    // 2. QKV projection -> bf16 hi/lo (Q pre-scaled)
    gemm_mma<4><<<dim3(D3 / 128, Mrows / 128), 256, GSMEM_SIZE>>>(
        xh, xl, wah, wal, b_attn, nullptr, nullptr, qvh, qvl, Mrows, D3, Dm);
    // 3. Flash attention (mma, 64-q tiles, longest-first) -> ctx hi/lo
    flash_mma<<<dim3(SEQ / 64, BATCH * NHEAD), 128, FSMEM>>>(qvh, qvl, ch, cl);
    // 4. cproj + residual -> h (fp32)
    gemm_mma<2><<<dim3(Dm / 128, Mrows / 128), 256, GSMEM_SIZE>>>(
        ch, cl, wch, wcl, b_cproj, hidden, h, nullptr, nullptr, Mrows, Dm, Dm);
    // 5. LN2 -> yln hi/lo
    layernorm_hilo<<<Mrows, 256>>>(h, ln2_g, ln2_b, yh, yl);
    // 6. fc + GELU -> act hi/lo
    gemm_mma<3><<<dim3(INNERD / 128, Mrows / 128), 256, GSMEM_SIZE>>>(
        yh, yl, wfh, wfl, b_fc, nullptr, nullptr, ah, al, Mrows, INNERD, Dm);
    // 7. fc_proj + residual -> out
    gemm_mma<2><<<dim3(Dm / 128, Mrows / 128), 256, GSMEM_SIZE>>>(
        ah, al, wph, wpl, b_fc_proj, h, out, nullptr, nullptr, Mrows, Dm, INNERD);
}